// round 11
// baseline (speedup 1.0000x reference)
#include <cuda_runtime.h>
#include <cuda_bf16.h>
#include <cuda_fp16.h>
#include <cstdint>

#define N 4096
#define FIN 512
#define FOUT 256
#define ALPHA 0.2f
#define JSPLIT 4
#define KCTA (N / JSPLIT)   // 1024
#define NCHUNK (KCTA / 64)  // 16

// ---------------- device scratch ----------------
__device__ float g_wh[N * FOUT];
__device__ float g_fsrc[N];
__device__ float g_fdst[N];
__device__ float g_u[N];                                     // rz*exp(fs-m)
__device__ float g_p[N];                                     // rz*exp(0.2fs-m)
__device__ __align__(16) float2 g_ef[N];                     // (exp(fd), exp(0.2fd))
__device__ unsigned g_mask[N * (N / 32)];                    // 2 MB
__device__ __align__(16) __half g_wh_h[N * FOUT];            // 2 MB [j][d] fp16
__device__ __align__(16) float g_part[(size_t)JSPLIT * N * FOUT];  // 16 MB

// ---------------- base-ISA PTX helpers ----------------
__device__ __forceinline__ uint32_t smem_u32(const void* p) {
    uint32_t a;
    asm("{ .reg .u64 t; cvta.to.shared.u64 t, %1; cvt.u32.u64 %0, t; }" : "=r"(a) : "l"(p));
    return a;
}
__device__ __forceinline__ void ldm_x4(uint32_t* r, uint32_t addr) {
    asm volatile("ldmatrix.sync.aligned.m8n8.x4.shared.b16 {%0,%1,%2,%3}, [%4];"
                 : "=r"(r[0]), "=r"(r[1]), "=r"(r[2]), "=r"(r[3]) : "r"(addr));
}
__device__ __forceinline__ void ldm_x4_t(uint32_t* r, uint32_t addr) {
    asm volatile("ldmatrix.sync.aligned.m8n8.x4.trans.shared.b16 {%0,%1,%2,%3}, [%4];"
                 : "=r"(r[0]), "=r"(r[1]), "=r"(r[2]), "=r"(r[3]) : "r"(addr));
}
__device__ __forceinline__ void mma_f16(float* c, const uint32_t* a, const uint32_t* b) {
    asm volatile(
        "mma.sync.aligned.m16n8k16.row.col.f32.f16.f16.f32 "
        "{%0,%1,%2,%3}, {%4,%5,%6,%7}, {%8,%9}, {%0,%1,%2,%3};"
        : "+f"(c[0]), "+f"(c[1]), "+f"(c[2]), "+f"(c[3])
        : "r"(a[0]), "r"(a[1]), "r"(a[2]), "r"(a[3]), "r"(b[0]), "r"(b[1]));
}
#define CP_ASYNC16(dst, src) \
    asm volatile("cp.async.cg.shared.global [%0], [%1], 16;" :: "r"(dst), "l"(src))
#define CP_COMMIT() asm volatile("cp.async.commit_group;" ::: "memory")
#define CP_WAIT0() asm volatile("cp.async.wait_group 0;" ::: "memory")

// ---------------- f32x2 helpers ----------------
__device__ __forceinline__ unsigned long long pk(float lo, float hi) {
    unsigned long long r;
    asm("mov.b64 %0, {%1,%2};" : "=l"(r) : "f"(lo), "f"(hi));
    return r;
}
__device__ __forceinline__ unsigned long long f2fma(unsigned long long a,
                                                    unsigned long long b,
                                                    unsigned long long c) {
    unsigned long long d;
    asm("fma.rn.f32x2 %0, %1, %2, %3;" : "=l"(d) : "l"(a), "l"(b), "l"(c));
    return d;
}
__device__ __forceinline__ float lof(unsigned long long v) { return __uint_as_float((unsigned)v); }
__device__ __forceinline__ float hif(unsigned long long v) { return __uint_as_float((unsigned)(v >> 32)); }

// ---------------- kernel 1: wh = h @ W + b, plus fp16 cast ------------------
__global__ __launch_bounds__(256) void k_gemm_wh(const float* __restrict__ h,
                                                 const float* __restrict__ Wm,
                                                 const float* __restrict__ bias) {
    __shared__ float As[64][33];
    __shared__ float Bs[32][64];
    const int t = threadIdx.x;
    const int m0 = blockIdx.x * 64, n0 = blockIdx.y * 64;
    const int tx = t & 15, ty = t >> 4;
    unsigned long long acc2[4][2];
#pragma unroll
    for (int i = 0; i < 4; i++) { acc2[i][0] = 0ull; acc2[i][1] = 0ull; }
    for (int k0 = 0; k0 < FIN; k0 += 32) {
#pragma unroll
        for (int u = 0; u < 2; u++) {
            int idx = t + u * 256, r = idx >> 3, c = (idx & 7) * 4;
            float4 v = *(const float4*)(h + (size_t)(m0 + r) * FIN + k0 + c);
            As[r][c] = v.x; As[r][c + 1] = v.y; As[r][c + 2] = v.z; As[r][c + 3] = v.w;
        }
#pragma unroll
        for (int u = 0; u < 2; u++) {
            int idx = t + u * 256, r = idx >> 4, c = (idx & 15) * 4;
            *(float4*)(&Bs[r][c]) = *(const float4*)(Wm + (size_t)(k0 + r) * FOUT + n0 + c);
        }
        __syncthreads();
#pragma unroll
        for (int k = 0; k < 32; k++) {
            double2 bd = *(const double2*)(&Bs[k][tx * 4]);
            unsigned long long b01 = __double_as_longlong(bd.x);
            unsigned long long b23 = __double_as_longlong(bd.y);
#pragma unroll
            for (int i = 0; i < 4; i++) {
                float a = As[ty * 4 + i][k];
                unsigned long long ap = pk(a, a);
                acc2[i][0] = f2fma(ap, b01, acc2[i][0]);
                acc2[i][1] = f2fma(ap, b23, acc2[i][1]);
            }
        }
        __syncthreads();
    }
    const int n = n0 + tx * 4;
    float4 bv = *(const float4*)(bias + n);
#pragma unroll
    for (int i = 0; i < 4; i++) {
        float4 o;
        o.x = lof(acc2[i][0]) + bv.x; o.y = hif(acc2[i][0]) + bv.y;
        o.z = lof(acc2[i][1]) + bv.z; o.w = hif(acc2[i][1]) + bv.w;
        size_t gi = (size_t)(m0 + ty * 4 + i) * FOUT + n;
        *(float4*)(g_wh + gi) = o;
        __half2 ha = __floats2half2_rn(o.x, o.y);
        __half2 hb = __floats2half2_rn(o.z, o.w);
        *(uint2*)(g_wh_h + gi) = make_uint2(*(unsigned*)&ha, *(unsigned*)&hb);
    }
}

// ---------------- kernel 2: f_src / f_dst + exp factors ----------------
__global__ __launch_bounds__(256) void k_fsd(const float* __restrict__ a1,
                                             const float* __restrict__ a2,
                                             const float* __restrict__ ab) {
    const int warp = threadIdx.x >> 5, lane = threadIdx.x & 31;
    const int i = blockIdx.x * 8 + warp;
    const float4* row = (const float4*)(g_wh + (size_t)i * FOUT);
    const float4* A1 = (const float4*)a1;
    const float4* A2 = (const float4*)a2;
    float s1 = 0.f, s2 = 0.f;
#pragma unroll
    for (int u = 0; u < 2; u++) {
        float4 v = row[lane + u * 32], x = A1[lane + u * 32], y = A2[lane + u * 32];
        s1 += v.x * x.x + v.y * x.y + v.z * x.z + v.w * x.w;
        s2 += v.x * y.x + v.y * y.y + v.z * y.z + v.w * y.w;
    }
#pragma unroll
    for (int o = 16; o; o >>= 1) {
        s1 += __shfl_down_sync(0xffffffffu, s1, o);
        s2 += __shfl_down_sync(0xffffffffu, s2, o);
    }
    if (lane == 0) {
        g_fsrc[i] = s1 + ab[0];
        g_fdst[i] = s2;
        g_ef[i] = make_float2(__expf(s2), __expf(ALPHA * s2));
    }
}

// ---------------- kernel 3: softmax stats + bit-pack → U_i, P_i -------------
__global__ __launch_bounds__(256) void k_prep(const int* __restrict__ adj) {
    const int i = blockIdx.x, t = threadIdx.x;
    const float fs = g_fsrc[i];
    const int4* arow = (const int4*)(adj + (size_t)i * N);
    const float4* fdp = (const float4*)g_fdst;

    float fdv[16];
    unsigned bits = 0;
#pragma unroll
    for (int u = 0; u < 4; u++) {
        int idx = u * 256 + t;              // coalesced: stride-1 across warp
        int4 a = arow[idx];
        float4 f = fdp[idx];
        fdv[u * 4 + 0] = f.x; fdv[u * 4 + 1] = f.y;
        fdv[u * 4 + 2] = f.z; fdv[u * 4 + 3] = f.w;
        unsigned nib = 0;
        if (a.x > 0) nib |= 1u;
        if (a.y > 0) nib |= 2u;
        if (a.z > 0) nib |= 4u;
        if (a.w > 0) nib |= 8u;
        bits |= nib << (u * 4);
        unsigned v = nib << ((t & 7) * 4);
        v |= __shfl_xor_sync(0xffffffffu, v, 1);
        v |= __shfl_xor_sync(0xffffffffu, v, 2);
        v |= __shfl_xor_sync(0xffffffffu, v, 4);
        if ((t & 7) == 0) g_mask[(size_t)i * 128 + u * 32 + (t >> 3)] = v;
    }

    float mx = -3.4e38f;
#pragma unroll
    for (int v = 0; v < 16; v++)
        if ((bits >> v) & 1u) mx = fmaxf(mx, fdv[v]);
#pragma unroll
    for (int o = 16; o; o >>= 1) mx = fmaxf(mx, __shfl_xor_sync(0xffffffffu, mx, o));
    __shared__ float redm[8];
    __shared__ float reds[8];
    if ((t & 31) == 0) redm[t >> 5] = mx;
    __syncthreads();
    float mxall = redm[0];
#pragma unroll
    for (int w = 1; w < 8; w++) mxall = fmaxf(mxall, redm[w]);
    float xm = fs + mxall;
    float mi = fmaxf(xm, ALPHA * xm);

    float s = 0.f;
#pragma unroll
    for (int v = 0; v < 16; v++)
        if ((bits >> v) & 1u) {
            float x = fs + fdv[v];
            s += __expf(fmaxf(x, ALPHA * x) - mi);
        }
#pragma unroll
    for (int o = 16; o; o >>= 1) s += __shfl_xor_sync(0xffffffffu, s, o);
    if ((t & 31) == 0) reds[t >> 5] = s;
    __syncthreads();
    if (t == 0) {
        float stot = 0.f;
#pragma unroll
        for (int w = 0; w < 8; w++) stot += reds[w];
        float rz = (stot > 0.f) ? (1.f / stot) : 0.f;
        g_u[i] = (rz > 0.f) ? rz * __expf(fs - mi) : 0.f;
        g_p[i] = (rz > 0.f) ? rz * __expf(ALPHA * fs - mi) : 0.f;
    }
}

// ---------------- kernel 4: HMMA attention GEMM, rank-1 weights -------------
// CTA tile M=128, N=256, K=1024 (16 chunks of 64). 1024 thr / 32 warps.
// warp grid: mw = warp>>3 (four 32-row groups, 2 m-tiles each), nw = warp&7.
// smem: EF 8KB | mask 16KB | 2 stages x 51KB {A 128x144B | B 64x528B}
#define SM_EF 0
#define SM_MASK 8192
#define SM_STG0 24576
#define A_OFF 0
#define B_OFF 18432
#define STG 52224
#define SMEM_AT (SM_STG0 + 2 * STG)  // 128 KB

__global__ __launch_bounds__(1024, 1) void k_attn_h() {
    extern __shared__ char smem[];
    const uint32_t sbase = smem_u32(smem);
    float2* ef_s = (float2*)(smem + SM_EF);
    unsigned* mask_s = (unsigned*)(smem + SM_MASK);
    const int t = threadIdx.x;
    const int lane = t & 31, warp = t >> 5;
    const int mw = warp >> 3, nw = warp & 7;
    const int i0 = blockIdx.x * 128;
    const int js = blockIdx.y;
    const int jorg = js * KCTA;

    // per-thread A-gen constants: thread generates weights for row i = t>>3
    const int gi = i0 + (t >> 3);
    const float eth = __expf(-g_fsrc[gi]);   // branch test: E_j >= eth <=> x >= 0
    const float ui = g_u[gi];
    const float pi = g_p[gi];

    // preload EF (1024 float2) + mask (128 rows x 32 words = 4096)
    if (t < 512) *(float4*)(ef_s + t * 2) = *(const float4*)(g_ef + jorg + t * 2);
#pragma unroll
    for (int u = 0; u < 4; u++) {
        int idx = t + 1024 * u;
        mask_s[idx] = g_mask[(size_t)(i0 + (idx >> 5)) * 128 + js * 32 + (idx & 31)];
    }
    __syncthreads();

    auto fill_B = [&](int c2, uint32_t stg_s) {
        size_t jg = (size_t)jorg + (size_t)c2 * 64;
#pragma unroll
        for (int u = 0; u < 2; u++) {
            int idx = t + 1024 * u;
            int j = idx >> 5, dq = idx & 31;
            uint32_t dst = stg_s + B_OFF + j * 528 + dq * 16;
            size_t src = (jg + j) * FOUT + dq * 8;
            CP_ASYNC16(dst, (const void*)(g_wh_h + src));
        }
    };
    // each thread: row t>>3 (0..127), j-octet t&7 (8 j values), rank-1 weights
    auto fill_A = [&](int c2, char* stgp) {
        const int row = t >> 3, oct = t & 7;
        unsigned w = mask_s[row * 32 + c2 * 2 + (oct >> 2)] >> ((oct & 3) * 8);
        const float2* efp = ef_s + c2 * 64 + oct * 8;
        uint32_t hv[4];
#pragma unroll
        for (int v = 0; v < 8; v += 2) {
            float4 q = *(const float4*)(efp + v);   // (E0,F0,E1,F1)
            float w0 = (q.x >= eth) ? ui * q.x : pi * q.y;
            float w1 = (q.z >= eth) ? ui * q.z : pi * q.w;
            if (!((w >> v) & 1u)) w0 = 0.f;
            if (!((w >> (v + 1)) & 1u)) w1 = 0.f;
            __half2 h2 = __floats2half2_rn(w0, w1);
            hv[v >> 1] = *(uint32_t*)&h2;
        }
        *(uint4*)(stgp + A_OFF + row * 144 + oct * 16) =
            make_uint4(hv[0], hv[1], hv[2], hv[3]);
    };

    float acc[2][4][4];
#pragma unroll
    for (int a = 0; a < 2; a++)
#pragma unroll
        for (int b = 0; b < 4; b++)
#pragma unroll
            for (int c = 0; c < 4; c++) acc[a][b][c] = 0.f;

    // ldmatrix per-thread base offsets
    const uint32_t a_off = (mw * 32 + (lane & 15)) * 144 + (lane >> 4) * 16;
    const uint32_t b_off = (lane & 15) * 528 + (nw * 32 + (lane >> 4) * 8) * 2;

    // prolog: fill chunk 0 into stage 0
    fill_B(0, sbase + SM_STG0);
    CP_COMMIT();
    fill_A(0, smem + SM_STG0);
    CP_WAIT0();
    __syncthreads();

#pragma unroll 1
    for (int c = 0; c < NCHUNK; c++) {
        const int s = c & 1;
        const uint32_t stg = SM_STG0 + (uint32_t)s * STG;
        const uint32_t stg2 = SM_STG0 + (uint32_t)(s ^ 1) * STG;
        const uint32_t Aa = sbase + stg + A_OFF;
        const uint32_t Bb = sbase + stg + B_OFF;

        if (c + 1 < NCHUNK) { fill_B(c + 1, sbase + stg2); CP_COMMIT(); }

#pragma unroll
        for (int kk = 0; kk < 4; kk++) {
            uint32_t bh[2][4];
            const uint32_t ao = a_off + kk * 32;
            const uint32_t bo = b_off + kk * 8448;
#pragma unroll
            for (int seg = 0; seg < 2; seg++)
                ldm_x4_t(bh[seg], Bb + bo + seg * 32);
#pragma unroll
            for (int mt = 0; mt < 2; mt++) {
                uint32_t ah[4];
                ldm_x4(ah, Aa + ao + mt * (16 * 144));
#pragma unroll
                for (int nb = 0; nb < 4; nb++) {
                    const uint32_t* bf = &bh[nb >> 1][(nb & 1) * 2];
                    mma_f16(acc[mt][nb], ah, bf);
                }
            }
            if (kk == 0 && c + 1 < NCHUNK) fill_A(c + 1, smem + stg2);
        }

        CP_WAIT0();
        __syncthreads();
    }

    // epilogue: write partials
    float* base = g_part + (size_t)js * ((size_t)N * FOUT);
#pragma unroll
    for (int mt = 0; mt < 2; mt++) {
        int ir = i0 + mw * 32 + mt * 16 + (lane >> 2);
#pragma unroll
        for (int nb = 0; nb < 4; nb++) {
            int d = nw * 32 + nb * 8 + (lane & 3) * 2;
            *(float2*)(base + (size_t)ir * FOUT + d) =
                make_float2(acc[mt][nb][0], acc[mt][nb][1]);
            *(float2*)(base + (size_t)(ir + 8) * FOUT + d) =
                make_float2(acc[mt][nb][2], acc[mt][nb][3]);
        }
    }
}

// ---------------- kernel 5: combine partials + elu ----------------
__global__ __launch_bounds__(256) void k_comb(float* __restrict__ out) {
    const size_t idx = ((size_t)blockIdx.x * 256 + threadIdx.x) * 4;
    const size_t stride = (size_t)N * FOUT;
    float4 a = *(const float4*)(g_part + idx);
    float4 b = *(const float4*)(g_part + stride + idx);
    float4 c = *(const float4*)(g_part + 2 * stride + idx);
    float4 d = *(const float4*)(g_part + 3 * stride + idx);
    float4 o;
    o.x = (a.x + b.x) + (c.x + d.x);
    o.y = (a.y + b.y) + (c.y + d.y);
    o.z = (a.z + b.z) + (c.z + d.z);
    o.w = (a.w + b.w) + (c.w + d.w);
    o.x = o.x > 0.f ? o.x : (__expf(o.x) - 1.f);
    o.y = o.y > 0.f ? o.y : (__expf(o.y) - 1.f);
    o.z = o.z > 0.f ? o.z : (__expf(o.z) - 1.f);
    o.w = o.w > 0.f ? o.w : (__expf(o.w) - 1.f);
    *(float4*)(out + idx) = o;
}

// ---------------- launch ----------------
extern "C" void kernel_launch(void* const* d_in, const int* in_sizes, int n_in,
                              void* d_out, int out_size) {
    const int* adj = (const int*)d_in[0];
    const float* h = (const float*)d_in[1];
    const float* Wm = (const float*)d_in[2];
    const float* b = (const float*)d_in[3];
    const float* a1 = (const float*)d_in[4];
    const float* a2 = (const float*)d_in[5];
    const float* ab = (const float*)d_in[6];
    float* out = (float*)d_out;

    static bool attr_set = false;
    if (!attr_set) {
        cudaFuncSetAttribute(k_attn_h, cudaFuncAttributeMaxDynamicSharedMemorySize, SMEM_AT);
        attr_set = true;
    }

    k_gemm_wh<<<dim3(N / 64, FOUT / 64), 256>>>(h, Wm, b);
    k_fsd<<<N / 8, 256>>>(a1, a2, ab);
    k_prep<<<N, 256>>>(adj);
    k_attn_h<<<dim3(N / 128, JSPLIT), 1024, SMEM_AT>>>();
    k_comb<<<(N * FOUT) / 1024, 256>>>(out);
}

// round 12
// speedup vs baseline: 1.0858x; 1.0858x over previous
#include <cuda_runtime.h>
#include <cuda_bf16.h>
#include <cuda_fp16.h>
#include <cstdint>

#define N 4096
#define FIN 512
#define FOUT 256
#define ALPHA 0.2f
#define JSPLIT 4
#define KCTA (N / JSPLIT)   // 1024
#define NCHUNK (KCTA / 64)  // 16

// ---------------- device scratch ----------------
__device__ float g_wh[N * FOUT];
__device__ float g_fsrc[N];   // zeroed per launch; atomically accumulated; +ab by k_prep
__device__ float g_fdst[N];   // zeroed per launch; atomically accumulated
__device__ float g_mi[N];
__device__ float g_rz[N];
__device__ unsigned g_mask[N * (N / 32)];                    // 2 MB
__device__ __align__(16) __half g_wh_h[N * FOUT];            // 2 MB [j][d] fp16
__device__ __align__(16) __half g_part_h[(size_t)JSPLIT * N * FOUT];  // 8 MB fp16 partials

// ---------------- base-ISA PTX helpers ----------------
__device__ __forceinline__ uint32_t smem_u32(const void* p) {
    uint32_t a;
    asm("{ .reg .u64 t; cvta.to.shared.u64 t, %1; cvt.u32.u64 %0, t; }" : "=r"(a) : "l"(p));
    return a;
}
__device__ __forceinline__ void ldm_x4(uint32_t* r, uint32_t addr) {
    asm volatile("ldmatrix.sync.aligned.m8n8.x4.shared.b16 {%0,%1,%2,%3}, [%4];"
                 : "=r"(r[0]), "=r"(r[1]), "=r"(r[2]), "=r"(r[3]) : "r"(addr));
}
__device__ __forceinline__ void ldm_x4_t(uint32_t* r, uint32_t addr) {
    asm volatile("ldmatrix.sync.aligned.m8n8.x4.trans.shared.b16 {%0,%1,%2,%3}, [%4];"
                 : "=r"(r[0]), "=r"(r[1]), "=r"(r[2]), "=r"(r[3]) : "r"(addr));
}
__device__ __forceinline__ void mma_f16(float* c, const uint32_t* a, const uint32_t* b) {
    asm volatile(
        "mma.sync.aligned.m16n8k16.row.col.f32.f16.f16.f32 "
        "{%0,%1,%2,%3}, {%4,%5,%6,%7}, {%8,%9}, {%0,%1,%2,%3};"
        : "+f"(c[0]), "+f"(c[1]), "+f"(c[2]), "+f"(c[3])
        : "r"(a[0]), "r"(a[1]), "r"(a[2]), "r"(a[3]), "r"(b[0]), "r"(b[1]));
}
#define CP_ASYNC16(dst, src) \
    asm volatile("cp.async.cg.shared.global [%0], [%1], 16;" :: "r"(dst), "l"(src))
#define CP_COMMIT() asm volatile("cp.async.commit_group;" ::: "memory")
#define CP_WAIT0() asm volatile("cp.async.wait_group 0;" ::: "memory")

// ---------------- f32x2 helpers ----------------
__device__ __forceinline__ unsigned long long pk(float lo, float hi) {
    unsigned long long r;
    asm("mov.b64 %0, {%1,%2};" : "=l"(r) : "f"(lo), "f"(hi));
    return r;
}
__device__ __forceinline__ unsigned long long f2fma(unsigned long long a,
                                                    unsigned long long b,
                                                    unsigned long long c) {
    unsigned long long d;
    asm("fma.rn.f32x2 %0, %1, %2, %3;" : "=l"(d) : "l"(a), "l"(b), "l"(c));
    return d;
}
__device__ __forceinline__ float lof(unsigned long long v) { return __uint_as_float((unsigned)v); }
__device__ __forceinline__ float hif(unsigned long long v) { return __uint_as_float((unsigned)(v >> 32)); }

// ---- kernel 1: wh = h @ W + b, fp16 cast, fused f_src/f_dst partial dots ----
__global__ __launch_bounds__(256) void k_gemm_wh(const float* __restrict__ h,
                                                 const float* __restrict__ Wm,
                                                 const float* __restrict__ bias,
                                                 const float* __restrict__ a1,
                                                 const float* __restrict__ a2) {
    __shared__ float As[64][33];
    __shared__ float Bs[32][64];
    const int t = threadIdx.x;
    const int m0 = blockIdx.x * 64, n0 = blockIdx.y * 64;
    const int tx = t & 15, ty = t >> 4;
    unsigned long long acc2[4][2];
#pragma unroll
    for (int i = 0; i < 4; i++) { acc2[i][0] = 0ull; acc2[i][1] = 0ull; }
    for (int k0 = 0; k0 < FIN; k0 += 32) {
#pragma unroll
        for (int u = 0; u < 2; u++) {
            int idx = t + u * 256, r = idx >> 3, c = (idx & 7) * 4;
            float4 v = *(const float4*)(h + (size_t)(m0 + r) * FIN + k0 + c);
            As[r][c] = v.x; As[r][c + 1] = v.y; As[r][c + 2] = v.z; As[r][c + 3] = v.w;
        }
#pragma unroll
        for (int u = 0; u < 2; u++) {
            int idx = t + u * 256, r = idx >> 4, c = (idx & 15) * 4;
            *(float4*)(&Bs[r][c]) = *(const float4*)(Wm + (size_t)(k0 + r) * FOUT + n0 + c);
        }
        __syncthreads();
#pragma unroll
        for (int k = 0; k < 32; k++) {
            double2 bd = *(const double2*)(&Bs[k][tx * 4]);
            unsigned long long b01 = __double_as_longlong(bd.x);
            unsigned long long b23 = __double_as_longlong(bd.y);
#pragma unroll
            for (int i = 0; i < 4; i++) {
                float a = As[ty * 4 + i][k];
                unsigned long long ap = pk(a, a);
                acc2[i][0] = f2fma(ap, b01, acc2[i][0]);
                acc2[i][1] = f2fma(ap, b23, acc2[i][1]);
            }
        }
        __syncthreads();
    }
    const int n = n0 + tx * 4;
    float4 bv = *(const float4*)(bias + n);
    float4 va1 = *(const float4*)(a1 + n);
    float4 va2 = *(const float4*)(a2 + n);
#pragma unroll
    for (int i = 0; i < 4; i++) {
        float4 o;
        o.x = lof(acc2[i][0]) + bv.x; o.y = hif(acc2[i][0]) + bv.y;
        o.z = lof(acc2[i][1]) + bv.z; o.w = hif(acc2[i][1]) + bv.w;
        const int row = m0 + ty * 4 + i;
        size_t gi = (size_t)row * FOUT + n;
        *(float4*)(g_wh + gi) = o;
        __half2 ha = __floats2half2_rn(o.x, o.y);
        __half2 hb = __floats2half2_rn(o.z, o.w);
        *(uint2*)(g_wh_h + gi) = make_uint2(*(unsigned*)&ha, *(unsigned*)&hb);
        // fused f_src / f_dst partial dots: reduce over 16 tx lanes (width 16)
        float s1 = o.x * va1.x + o.y * va1.y + o.z * va1.z + o.w * va1.w;
        float s2 = o.x * va2.x + o.y * va2.y + o.z * va2.z + o.w * va2.w;
#pragma unroll
        for (int off = 8; off; off >>= 1) {
            s1 += __shfl_down_sync(0xffffffffu, s1, off, 16);
            s2 += __shfl_down_sync(0xffffffffu, s2, off, 16);
        }
        if (tx == 0) {
            atomicAdd(g_fsrc + row, s1);
            atomicAdd(g_fdst + row, s2);
        }
    }
}

// ---------------- kernel 3: softmax stats + bit-pack (coalesced int4) -------
__global__ __launch_bounds__(256) void k_prep(const int* __restrict__ adj,
                                              const float* __restrict__ ab) {
    const int i = blockIdx.x, t = threadIdx.x;
    const float fs = g_fsrc[i] + ab[0];
    const int4* arow = (const int4*)(adj + (size_t)i * N);
    const float4* fdp = (const float4*)g_fdst;

    float fdv[16];
    unsigned bits = 0;
#pragma unroll
    for (int u = 0; u < 4; u++) {
        int idx = u * 256 + t;              // coalesced: stride-1 across warp
        int4 a = arow[idx];
        float4 f = fdp[idx];
        fdv[u * 4 + 0] = f.x; fdv[u * 4 + 1] = f.y;
        fdv[u * 4 + 2] = f.z; fdv[u * 4 + 3] = f.w;
        unsigned nib = 0;
        if (a.x > 0) nib |= 1u;
        if (a.y > 0) nib |= 2u;
        if (a.z > 0) nib |= 4u;
        if (a.w > 0) nib |= 8u;
        bits |= nib << (u * 4);
        unsigned v = nib << ((t & 7) * 4);
        v |= __shfl_xor_sync(0xffffffffu, v, 1);
        v |= __shfl_xor_sync(0xffffffffu, v, 2);
        v |= __shfl_xor_sync(0xffffffffu, v, 4);
        if ((t & 7) == 0) g_mask[(size_t)i * 128 + u * 32 + (t >> 3)] = v;
    }

    float mx = -3.4e38f;
#pragma unroll
    for (int v = 0; v < 16; v++)
        if ((bits >> v) & 1u) mx = fmaxf(mx, fdv[v]);
#pragma unroll
    for (int o = 16; o; o >>= 1) mx = fmaxf(mx, __shfl_xor_sync(0xffffffffu, mx, o));
    __shared__ float redm[8];
    __shared__ float reds[8];
    if ((t & 31) == 0) redm[t >> 5] = mx;
    __syncthreads();
    float mxall = redm[0];
#pragma unroll
    for (int w = 1; w < 8; w++) mxall = fmaxf(mxall, redm[w]);
    float xm = fs + mxall;
    float mi = fmaxf(xm, ALPHA * xm);

    float s = 0.f;
#pragma unroll
    for (int v = 0; v < 16; v++)
        if ((bits >> v) & 1u) {
            float x = fs + fdv[v];
            s += __expf(fmaxf(x, ALPHA * x) - mi);
        }
#pragma unroll
    for (int o = 16; o; o >>= 1) s += __shfl_xor_sync(0xffffffffu, s, o);
    if ((t & 31) == 0) reds[t >> 5] = s;
    __syncthreads();
    if (t == 0) {
        float stot = 0.f;
#pragma unroll
        for (int w = 0; w < 8; w++) stot += reds[w];
        g_mi[i] = mi;
        g_rz[i] = (stot > 0.f) ? (1.f / stot) : 0.f;
        g_fsrc[i] = fs;   // write back ab-inclusive f_src for k_attn
    }
}

// ---------------- kernel 4: HMMA attention GEMM (R10 form, fp16 partials) ---
// CTA tile M=128, N=256, K=1024 (16 chunks of 64). 1024 thr / 32 warps.
// warp grid: mw = warp>>3 (four 32-row groups, 2 m-tiles each), nw = warp&7.
#define SM_FD 0
#define SM_MASK 4096
#define SM_STG0 20480
#define A_OFF 0
#define B_OFF 18432
#define STG 52224
#define SMEM_AT (SM_STG0 + 2 * STG)  // 124928

__global__ __launch_bounds__(1024, 1) void k_attn_h() {
    extern __shared__ char smem[];
    const uint32_t sbase = smem_u32(smem);
    float* fd_s = (float*)(smem + SM_FD);
    unsigned* mask_s = (unsigned*)(smem + SM_MASK);
    const int t = threadIdx.x;
    const int lane = t & 31, warp = t >> 5;
    const int mw = warp >> 3, nw = warp & 7;
    const int i0 = blockIdx.x * 128;
    const int js = blockIdx.y;
    const int jorg = js * KCTA;

    // per-thread A-gen constants: thread generates weights for row i = t>>3
    const int gi = i0 + (t >> 3);
    const float fsi = g_fsrc[gi];
    const float mii = g_mi[gi];
    const float rzi = g_rz[gi];

    // preload fd (1024 floats) + mask (128 rows x 32 words = 4096)
    if (t < 256) *(float4*)(fd_s + t * 4) = *(const float4*)(g_fdst + jorg + t * 4);
#pragma unroll
    for (int u = 0; u < 4; u++) {
        int idx = t + 1024 * u;
        mask_s[idx] = g_mask[(size_t)(i0 + (idx >> 5)) * 128 + js * 32 + (idx & 31)];
    }
    __syncthreads();

    auto fill_B = [&](int c2, uint32_t stg_s) {
        size_t jg = (size_t)jorg + (size_t)c2 * 64;
#pragma unroll
        for (int u = 0; u < 2; u++) {
            int idx = t + 1024 * u;
            int j = idx >> 5, dq = idx & 31;
            uint32_t dst = stg_s + B_OFF + j * 528 + dq * 16;
            size_t src = (jg + j) * FOUT + dq * 8;
            CP_ASYNC16(dst, (const void*)(g_wh_h + src));
        }
    };
    // each thread: row t>>3 (0..127), j-octet t&7 (8 j values), fp16
    auto fill_A = [&](int c2, char* stgp) {
        const int row = t >> 3, oct = t & 7;
        unsigned w = mask_s[row * 32 + c2 * 2 + (oct >> 2)] >> ((oct & 3) * 8);
        const float* fdp = fd_s + c2 * 64 + oct * 8;
        uint32_t hv[4];
#pragma unroll
        for (int v = 0; v < 8; v += 2) {
            float e0 = 0.f, e1 = 0.f;
            if ((w >> v) & 1u) {
                float x = fsi + fdp[v];
                e0 = __expf(fmaxf(x, ALPHA * x) - mii) * rzi;
            }
            if ((w >> (v + 1)) & 1u) {
                float x = fsi + fdp[v + 1];
                e1 = __expf(fmaxf(x, ALPHA * x) - mii) * rzi;
            }
            __half2 h2 = __floats2half2_rn(e0, e1);
            hv[v >> 1] = *(uint32_t*)&h2;
        }
        *(uint4*)(stgp + A_OFF + row * 144 + oct * 16) =
            make_uint4(hv[0], hv[1], hv[2], hv[3]);
    };

    float acc[2][4][4];
#pragma unroll
    for (int a = 0; a < 2; a++)
#pragma unroll
        for (int b = 0; b < 4; b++)
#pragma unroll
            for (int c = 0; c < 4; c++) acc[a][b][c] = 0.f;

    // ldmatrix per-thread base offsets
    const uint32_t a_off = (mw * 32 + (lane & 15)) * 144 + (lane >> 4) * 16;
    const uint32_t b_off = (lane & 15) * 528 + (nw * 32 + (lane >> 4) * 8) * 2;

    // prolog: fill chunk 0 into stage 0
    fill_B(0, sbase + SM_STG0);
    CP_COMMIT();
    fill_A(0, smem + SM_STG0);
    CP_WAIT0();
    __syncthreads();

#pragma unroll 1
    for (int c = 0; c < NCHUNK; c++) {
        const int s = c & 1;
        const uint32_t stg = SM_STG0 + (uint32_t)s * STG;
        const uint32_t stg2 = SM_STG0 + (uint32_t)(s ^ 1) * STG;
        const uint32_t Aa = sbase + stg + A_OFF;
        const uint32_t Bb = sbase + stg + B_OFF;

        if (c + 1 < NCHUNK) { fill_B(c + 1, sbase + stg2); CP_COMMIT(); }

#pragma unroll
        for (int kk = 0; kk < 4; kk++) {
            uint32_t bh[2][4];
            const uint32_t ao = a_off + kk * 32;
            const uint32_t bo = b_off + kk * 8448;
#pragma unroll
            for (int seg = 0; seg < 2; seg++)
                ldm_x4_t(bh[seg], Bb + bo + seg * 32);
#pragma unroll
            for (int mt = 0; mt < 2; mt++) {
                uint32_t ah[4];
                ldm_x4(ah, Aa + ao + mt * (16 * 144));
#pragma unroll
                for (int nb = 0; nb < 4; nb++) {
                    const uint32_t* bf = &bh[nb >> 1][(nb & 1) * 2];
                    mma_f16(acc[mt][nb], ah, bf);
                }
            }
            if (kk == 0 && c + 1 < NCHUNK) fill_A(c + 1, smem + stg2);
        }

        CP_WAIT0();
        __syncthreads();
    }

    // epilogue: write fp16 partials
    __half* base = g_part_h + (size_t)js * ((size_t)N * FOUT);
#pragma unroll
    for (int mt = 0; mt < 2; mt++) {
        int ir = i0 + mw * 32 + mt * 16 + (lane >> 2);
#pragma unroll
        for (int nb = 0; nb < 4; nb++) {
            int d = nw * 32 + nb * 8 + (lane & 3) * 2;
            __half2 p01 = __floats2half2_rn(acc[mt][nb][0], acc[mt][nb][1]);
            __half2 p23 = __floats2half2_rn(acc[mt][nb][2], acc[mt][nb][3]);
            *(uint32_t*)(base + (size_t)ir * FOUT + d) = *(uint32_t*)&p01;
            *(uint32_t*)(base + (size_t)(ir + 8) * FOUT + d) = *(uint32_t*)&p23;
        }
    }
}

// ---------------- kernel 5: combine fp16 partials + elu ----------------
__global__ __launch_bounds__(256) void k_comb(float* __restrict__ out) {
    const size_t idx = ((size_t)blockIdx.x * 256 + threadIdx.x) * 4;
    const size_t stride = (size_t)N * FOUT;
    float o[4] = {0.f, 0.f, 0.f, 0.f};
#pragma unroll
    for (int sp = 0; sp < JSPLIT; sp++) {
        uint2 u = *(const uint2*)(g_part_h + sp * stride + idx);
        float2 p0 = __half22float2(*(__half2*)&u.x);
        float2 p1 = __half22float2(*(__half2*)&u.y);
        o[0] += p0.x; o[1] += p0.y; o[2] += p1.x; o[3] += p1.y;
    }
    float4 r;
    r.x = o[0] > 0.f ? o[0] : (__expf(o[0]) - 1.f);
    r.y = o[1] > 0.f ? o[1] : (__expf(o[1]) - 1.f);
    r.z = o[2] > 0.f ? o[2] : (__expf(o[2]) - 1.f);
    r.w = o[3] > 0.f ? o[3] : (__expf(o[3]) - 1.f);
    *(float4*)(out + idx) = r;
}

// ---------------- launch ----------------
extern "C" void kernel_launch(void* const* d_in, const int* in_sizes, int n_in,
                              void* d_out, int out_size) {
    const int* adj = (const int*)d_in[0];
    const float* h = (const float*)d_in[1];
    const float* Wm = (const float*)d_in[2];
    const float* b = (const float*)d_in[3];
    const float* a1 = (const float*)d_in[4];
    const float* a2 = (const float*)d_in[5];
    const float* ab = (const float*)d_in[6];
    float* out = (float*)d_out;

    static bool inited = false;
    static void* fsrc_ptr = nullptr;
    static void* fdst_ptr = nullptr;
    if (!inited) {
        cudaFuncSetAttribute(k_attn_h, cudaFuncAttributeMaxDynamicSharedMemorySize, SMEM_AT);
        cudaGetSymbolAddress(&fsrc_ptr, g_fsrc);
        cudaGetSymbolAddress(&fdst_ptr, g_fdst);
        inited = true;
    }

    cudaMemsetAsync(fsrc_ptr, 0, N * sizeof(float));
    cudaMemsetAsync(fdst_ptr, 0, N * sizeof(float));
    k_gemm_wh<<<dim3(N / 64, FOUT / 64), 256>>>(h, Wm, b, a1, a2);
    k_prep<<<N, 256>>>(adj, ab);
    k_attn_h<<<dim3(N / 128, JSPLIT), 1024, SMEM_AT>>>();
    k_comb<<<(N * FOUT) / 1024, 256>>>(out);
}

// round 14
// speedup vs baseline: 1.2741x; 1.1734x over previous
#include <cuda_runtime.h>
#include <cuda_bf16.h>
#include <cuda_fp16.h>
#include <cstdint>

#define N 4096
#define FIN 512
#define FOUT 256
#define ALPHA 0.2f
#define JSPLIT 4
#define KCTA (N / JSPLIT)   // 1024
#define NCHUNK (KCTA / 64)  // 16

// ---------------- device scratch ----------------
__device__ float g_fsrc[N];   // zeroed per launch; atomically accumulated; +ab by k_prep
__device__ float g_fdst[N];   // zeroed per launch; atomically accumulated
__device__ float g_mi[N];
__device__ float g_rz[N];
__device__ unsigned g_mask[N * (N / 32)];                    // 2 MB
__device__ __align__(16) __half g_h_h[N * FIN];              // 4 MB h in fp16
__device__ __align__(16) __half g_W_hi[FIN * FOUT];          // 256 KB
__device__ __align__(16) __half g_W_lo[FIN * FOUT];          // 256 KB
__device__ __align__(16) __half g_wh_h[N * FOUT];            // 2 MB [j][d] fp16
__device__ __align__(16) __half g_part_h[(size_t)JSPLIT * N * FOUT];  // 8 MB fp16 partials

// ---------------- base-ISA PTX helpers ----------------
__device__ __forceinline__ uint32_t smem_u32(const void* p) {
    uint32_t a;
    asm("{ .reg .u64 t; cvta.to.shared.u64 t, %1; cvt.u32.u64 %0, t; }" : "=r"(a) : "l"(p));
    return a;
}
__device__ __forceinline__ void ldm_x4(uint32_t* r, uint32_t addr) {
    asm volatile("ldmatrix.sync.aligned.m8n8.x4.shared.b16 {%0,%1,%2,%3}, [%4];"
                 : "=r"(r[0]), "=r"(r[1]), "=r"(r[2]), "=r"(r[3]) : "r"(addr));
}
__device__ __forceinline__ void ldm_x4_t(uint32_t* r, uint32_t addr) {
    asm volatile("ldmatrix.sync.aligned.m8n8.x4.trans.shared.b16 {%0,%1,%2,%3}, [%4];"
                 : "=r"(r[0]), "=r"(r[1]), "=r"(r[2]), "=r"(r[3]) : "r"(addr));
}
__device__ __forceinline__ void mma_f16(float* c, const uint32_t* a, const uint32_t* b) {
    asm volatile(
        "mma.sync.aligned.m16n8k16.row.col.f32.f16.f16.f32 "
        "{%0,%1,%2,%3}, {%4,%5,%6,%7}, {%8,%9}, {%0,%1,%2,%3};"
        : "+f"(c[0]), "+f"(c[1]), "+f"(c[2]), "+f"(c[3])
        : "r"(a[0]), "r"(a[1]), "r"(a[2]), "r"(a[3]), "r"(b[0]), "r"(b[1]));
}
#define CP_ASYNC16(dst, src) \
    asm volatile("cp.async.cg.shared.global [%0], [%1], 16;" :: "r"(dst), "l"(src))
#define CP_COMMIT() asm volatile("cp.async.commit_group;" ::: "memory")
#define CP_WAIT0() asm volatile("cp.async.wait_group 0;" ::: "memory")

// ---------------- kernel 0: convert h -> fp16, W -> fp16 hi/lo --------------
__global__ __launch_bounds__(256) void k_cvt(const float* __restrict__ h,
                                             const float* __restrict__ Wm) {
    const int b = blockIdx.x, t = threadIdx.x;
    if (b < 2048) {  // h: 4096*512 = 2048*1024 floats
        size_t idx = (size_t)b * 1024 + t * 4;
        float4 v = *(const float4*)(h + idx);
        __half2 p0 = __floats2half2_rn(v.x, v.y);
        __half2 p1 = __floats2half2_rn(v.z, v.w);
        *(uint2*)(g_h_h + idx) = make_uint2(*(unsigned*)&p0, *(unsigned*)&p1);
    } else {         // W: 512*256 = 128*1024 floats
        size_t idx = (size_t)(b - 2048) * 1024 + t * 4;
        float4 v = *(const float4*)(Wm + idx);
        __half2 h0 = __floats2half2_rn(v.x, v.y);
        __half2 h1 = __floats2half2_rn(v.z, v.w);
        __half2 l0 = __floats2half2_rn(v.x - __half2float(h0.x), v.y - __half2float(h0.y));
        __half2 l1 = __floats2half2_rn(v.z - __half2float(h1.x), v.w - __half2float(h1.y));
        *(uint2*)(g_W_hi + idx) = make_uint2(*(unsigned*)&h0, *(unsigned*)&h1);
        *(uint2*)(g_W_lo + idx) = make_uint2(*(unsigned*)&l0, *(unsigned*)&l1);
    }
}

// ---------------- kernel 1: wh GEMM via HMMA (h fp16 x W hi/lo) -------------
// M=32 per CTA (128 CTAs), N=256, K=512 in 8 chunks of 64. 1024 thr / 32 warps.
// warp grid: mg = warp&1 (two 16-row halves), ns = warp>>1 (sixteen 16-col slices)
// epilogue: +bias, fp16 store, fused f_src/f_dst dots (atomicAdd)
#define WH_A 0
#define WH_BHI 4608
#define WH_BLO 38400
#define WH_STG 72192
#define SMEM_WH (2 * WH_STG)  // 144384

__global__ __launch_bounds__(1024, 1) void k_wh_h(const float* __restrict__ bias,
                                                  const float* __restrict__ a1,
                                                  const float* __restrict__ a2) {
    extern __shared__ char smem[];
    const uint32_t sbase = smem_u32(smem);
    const int t = threadIdx.x, lane = t & 31, warp = t >> 5;
    const int mg = warp & 1, ns = warp >> 1;
    const int i0 = blockIdx.x * 32;

    auto fill = [&](int c2, uint32_t stg) {
        const int k0 = c2 * 64;
        if (t < 256) {
            int row = t >> 3, cc = t & 7;
            CP_ASYNC16(stg + WH_A + row * 144 + cc * 16,
                       (const void*)(g_h_h + (size_t)(i0 + row) * FIN + k0 + cc * 8));
        }
        // B rows are 256 halves = 512 bytes: 64 rows x 32 chunks of 16B = 2048 ops
#pragma unroll
        for (int u = 0; u < 2; u++) {
            int idx = t + 1024 * u;
            int j = idx >> 5, dq = idx & 31;
            uint32_t dst = stg + WH_BHI + j * 528 + dq * 16;
            size_t src = (size_t)(k0 + j) * FOUT + dq * 8;
            CP_ASYNC16(dst, (const void*)(g_W_hi + src));
            CP_ASYNC16(dst + (WH_BLO - WH_BHI), (const void*)(g_W_lo + src));
        }
    };

    float acc[2][4];
#pragma unroll
    for (int b = 0; b < 2; b++)
#pragma unroll
        for (int c = 0; c < 4; c++) acc[b][c] = 0.f;

    const uint32_t a_off = (mg * 16 + (lane & 15)) * 144 + (lane >> 4) * 16;
    const uint32_t b_off = (lane & 15) * 528 + (ns * 16 + (lane >> 4) * 8) * 2;

    fill(0, sbase);
    CP_COMMIT();
    CP_WAIT0();
    __syncthreads();

#pragma unroll 1
    for (int c = 0; c < 8; c++) {
        const uint32_t stg = sbase + (uint32_t)(c & 1) * WH_STG;
        const uint32_t stg2 = sbase + (uint32_t)((c & 1) ^ 1) * WH_STG;
        if (c + 1 < 8) { fill(c + 1, stg2); CP_COMMIT(); }

#pragma unroll
        for (int kk = 0; kk < 4; kk++) {
            uint32_t ah[4], bh[4], bl[4];
            ldm_x4(ah, stg + WH_A + a_off + kk * 32);
            ldm_x4_t(bh, stg + WH_BHI + b_off + kk * 8448);
            ldm_x4_t(bl, stg + WH_BLO + b_off + kk * 8448);
            mma_f16(acc[0], ah, bh);
            mma_f16(acc[1], ah, bh + 2);
            mma_f16(acc[0], ah, bl);
            mma_f16(acc[1], ah, bl + 2);
        }
        CP_WAIT0();
        __syncthreads();
    }

    // epilogue: bias, fp16 store, f-dot atomics
    const int d0 = ns * 16 + (lane & 3) * 2;
    const int d1 = d0 + 8;
    const int ir = i0 + mg * 16 + (lane >> 2);
    float2 bv0 = *(const float2*)(bias + d0);
    float2 bv1 = *(const float2*)(bias + d1);
    float o00 = acc[0][0] + bv0.x, o01 = acc[0][1] + bv0.y;
    float o10 = acc[1][0] + bv1.x, o11 = acc[1][1] + bv1.y;
    float o20 = acc[0][2] + bv0.x, o21 = acc[0][3] + bv0.y;
    float o30 = acc[1][2] + bv1.x, o31 = acc[1][3] + bv1.y;

    __half2 p;
    p = __floats2half2_rn(o00, o01); *(uint32_t*)(g_wh_h + (size_t)ir * FOUT + d0) = *(uint32_t*)&p;
    p = __floats2half2_rn(o10, o11); *(uint32_t*)(g_wh_h + (size_t)ir * FOUT + d1) = *(uint32_t*)&p;
    p = __floats2half2_rn(o20, o21); *(uint32_t*)(g_wh_h + (size_t)(ir + 8) * FOUT + d0) = *(uint32_t*)&p;
    p = __floats2half2_rn(o30, o31); *(uint32_t*)(g_wh_h + (size_t)(ir + 8) * FOUT + d1) = *(uint32_t*)&p;

    float2 x0 = *(const float2*)(a1 + d0), x1 = *(const float2*)(a1 + d1);
    float2 y0 = *(const float2*)(a2 + d0), y1 = *(const float2*)(a2 + d1);
    float s1 = o00 * x0.x + o01 * x0.y + o10 * x1.x + o11 * x1.y;
    float s2 = o00 * y0.x + o01 * y0.y + o10 * y1.x + o11 * y1.y;
    float s1b = o20 * x0.x + o21 * x0.y + o30 * x1.x + o31 * x1.y;
    float s2b = o20 * y0.x + o21 * y0.y + o30 * y1.x + o31 * y1.y;
#pragma unroll
    for (int off = 1; off <= 2; off <<= 1) {
        s1 += __shfl_xor_sync(0xffffffffu, s1, off);
        s2 += __shfl_xor_sync(0xffffffffu, s2, off);
        s1b += __shfl_xor_sync(0xffffffffu, s1b, off);
        s2b += __shfl_xor_sync(0xffffffffu, s2b, off);
    }
    if ((lane & 3) == 0) {
        atomicAdd(g_fsrc + ir, s1);
        atomicAdd(g_fdst + ir, s2);
        atomicAdd(g_fsrc + ir + 8, s1b);
        atomicAdd(g_fdst + ir + 8, s2b);
    }
}

// ---------------- kernel 3: softmax stats + bit-pack (streaming int4) -------
__global__ __launch_bounds__(256) void k_prep(const int* __restrict__ adj,
                                              const float* __restrict__ ab) {
    const int i = blockIdx.x, t = threadIdx.x;
    const float fs = g_fsrc[i] + ab[0];
    const int4* arow = (const int4*)(adj + (size_t)i * N);
    const float4* fdp = (const float4*)g_fdst;

    float fdv[16];
    unsigned bits = 0;
#pragma unroll
    for (int u = 0; u < 4; u++) {
        int idx = u * 256 + t;              // coalesced: stride-1 across warp
        int4 a = __ldcs(arow + idx);        // streaming: no L2 reuse
        float4 f = fdp[idx];
        fdv[u * 4 + 0] = f.x; fdv[u * 4 + 1] = f.y;
        fdv[u * 4 + 2] = f.z; fdv[u * 4 + 3] = f.w;
        unsigned nib = 0;
        if (a.x > 0) nib |= 1u;
        if (a.y > 0) nib |= 2u;
        if (a.z > 0) nib |= 4u;
        if (a.w > 0) nib |= 8u;
        bits |= nib << (u * 4);
        unsigned v = nib << ((t & 7) * 4);
        v |= __shfl_xor_sync(0xffffffffu, v, 1);
        v |= __shfl_xor_sync(0xffffffffu, v, 2);
        v |= __shfl_xor_sync(0xffffffffu, v, 4);
        if ((t & 7) == 0) g_mask[(size_t)i * 128 + u * 32 + (t >> 3)] = v;
    }

    float mx = -3.4e38f;
#pragma unroll
    for (int v = 0; v < 16; v++)
        if ((bits >> v) & 1u) mx = fmaxf(mx, fdv[v]);
#pragma unroll
    for (int o = 16; o; o >>= 1) mx = fmaxf(mx, __shfl_xor_sync(0xffffffffu, mx, o));
    __shared__ float redm[8];
    __shared__ float reds[8];
    if ((t & 31) == 0) redm[t >> 5] = mx;
    __syncthreads();
    float mxall = redm[0];
#pragma unroll
    for (int w = 1; w < 8; w++) mxall = fmaxf(mxall, redm[w]);
    float xm = fs + mxall;
    float mi = fmaxf(xm, ALPHA * xm);

    float s = 0.f;
#pragma unroll
    for (int v = 0; v < 16; v++)
        if ((bits >> v) & 1u) {
            float x = fs + fdv[v];
            s += __expf(fmaxf(x, ALPHA * x) - mi);
        }
#pragma unroll
    for (int o = 16; o; o >>= 1) s += __shfl_xor_sync(0xffffffffu, s, o);
    if ((t & 31) == 0) reds[t >> 5] = s;
    __syncthreads();
    if (t == 0) {
        float stot = 0.f;
#pragma unroll
        for (int w = 0; w < 8; w++) stot += reds[w];
        g_mi[i] = mi;
        g_rz[i] = (stot > 0.f) ? (1.f / stot) : 0.f;
        g_fsrc[i] = fs;   // write back ab-inclusive f_src for k_attn
    }
}

// ---------------- kernel 4: HMMA attention GEMM (fp16, fp16 partials) -------
#define SM_FD 0
#define SM_MASK 4096
#define SM_STG0 20480
#define A_OFF 0
#define B_OFF 18432
#define STG 52224
#define SMEM_AT (SM_STG0 + 2 * STG)  // 124928

__global__ __launch_bounds__(1024, 1) void k_attn_h() {
    extern __shared__ char smem[];
    const uint32_t sbase = smem_u32(smem);
    float* fd_s = (float*)(smem + SM_FD);
    unsigned* mask_s = (unsigned*)(smem + SM_MASK);
    const int t = threadIdx.x;
    const int lane = t & 31, warp = t >> 5;
    const int mw = warp >> 3, nw = warp & 7;
    const int i0 = blockIdx.x * 128;
    const int js = blockIdx.y;
    const int jorg = js * KCTA;

    const int gi = i0 + (t >> 3);
    const float fsi = g_fsrc[gi];
    const float mii = g_mi[gi];
    const float rzi = g_rz[gi];

    if (t < 256) *(float4*)(fd_s + t * 4) = *(const float4*)(g_fdst + jorg + t * 4);
#pragma unroll
    for (int u = 0; u < 4; u++) {
        int idx = t + 1024 * u;
        mask_s[idx] = g_mask[(size_t)(i0 + (idx >> 5)) * 128 + js * 32 + (idx & 31)];
    }
    __syncthreads();

    auto fill_B = [&](int c2, uint32_t stg_s) {
        size_t jg = (size_t)jorg + (size_t)c2 * 64;
#pragma unroll
        for (int u = 0; u < 2; u++) {
            int idx = t + 1024 * u;
            int j = idx >> 5, dq = idx & 31;
            uint32_t dst = stg_s + B_OFF + j * 528 + dq * 16;
            size_t src = (jg + j) * FOUT + dq * 8;
            CP_ASYNC16(dst, (const void*)(g_wh_h + src));
        }
    };
    auto fill_A = [&](int c2, char* stgp) {
        const int row = t >> 3, oct = t & 7;
        unsigned w = mask_s[row * 32 + c2 * 2 + (oct >> 2)] >> ((oct & 3) * 8);
        const float* fdp = fd_s + c2 * 64 + oct * 8;
        uint32_t hv[4];
#pragma unroll
        for (int v = 0; v < 8; v += 2) {
            float e0 = 0.f, e1 = 0.f;
            if ((w >> v) & 1u) {
                float x = fsi + fdp[v];
                e0 = __expf(fmaxf(x, ALPHA * x) - mii) * rzi;
            }
            if ((w >> (v + 1)) & 1u) {
                float x = fsi + fdp[v + 1];
                e1 = __expf(fmaxf(x, ALPHA * x) - mii) * rzi;
            }
            __half2 h2 = __floats2half2_rn(e0, e1);
            hv[v >> 1] = *(uint32_t*)&h2;
        }
        *(uint4*)(stgp + A_OFF + row * 144 + oct * 16) =
            make_uint4(hv[0], hv[1], hv[2], hv[3]);
    };

    float acc[2][4][4];
#pragma unroll
    for (int a = 0; a < 2; a++)
#pragma unroll
        for (int b = 0; b < 4; b++)
#pragma unroll
            for (int c = 0; c < 4; c++) acc[a][b][c] = 0.f;

    const uint32_t a_off = (mw * 32 + (lane & 15)) * 144 + (lane >> 4) * 16;
    const uint32_t b_off = (lane & 15) * 528 + (nw * 32 + (lane >> 4) * 8) * 2;

    fill_B(0, sbase + SM_STG0);
    CP_COMMIT();
    fill_A(0, smem + SM_STG0);
    CP_WAIT0();
    __syncthreads();

#pragma unroll 1
    for (int c = 0; c < NCHUNK; c++) {
        const int s = c & 1;
        const uint32_t stg = SM_STG0 + (uint32_t)s * STG;
        const uint32_t stg2 = SM_STG0 + (uint32_t)(s ^ 1) * STG;
        const uint32_t Aa = sbase + stg + A_OFF;
        const uint32_t Bb = sbase + stg + B_OFF;

        if (c + 1 < NCHUNK) { fill_B(c + 1, sbase + stg2); CP_COMMIT(); }

#pragma unroll
        for (int kk = 0; kk < 4; kk++) {
            uint32_t bh[2][4];
            const uint32_t ao = a_off + kk * 32;
            const uint32_t bo = b_off + kk * 8448;
#pragma unroll
            for (int seg = 0; seg < 2; seg++)
                ldm_x4_t(bh[seg], Bb + bo + seg * 32);
#pragma unroll
            for (int mt = 0; mt < 2; mt++) {
                uint32_t ah[4];
                ldm_x4(ah, Aa + ao + mt * (16 * 144));
#pragma unroll
                for (int nb = 0; nb < 4; nb++) {
                    const uint32_t* bf = &bh[nb >> 1][(nb & 1) * 2];
                    mma_f16(acc[mt][nb], ah, bf);
                }
            }
            if (kk == 0 && c + 1 < NCHUNK) fill_A(c + 1, smem + stg2);
        }

        CP_WAIT0();
        __syncthreads();
    }

    __half* base = g_part_h + (size_t)js * ((size_t)N * FOUT);
#pragma unroll
    for (int mt = 0; mt < 2; mt++) {
        int ir = i0 + mw * 32 + mt * 16 + (lane >> 2);
#pragma unroll
        for (int nb = 0; nb < 4; nb++) {
            int d = nw * 32 + nb * 8 + (lane & 3) * 2;
            __half2 p01 = __floats2half2_rn(acc[mt][nb][0], acc[mt][nb][1]);
            __half2 p23 = __floats2half2_rn(acc[mt][nb][2], acc[mt][nb][3]);
            *(uint32_t*)(base + (size_t)ir * FOUT + d) = *(uint32_t*)&p01;
            *(uint32_t*)(base + (size_t)(ir + 8) * FOUT + d) = *(uint32_t*)&p23;
        }
    }
}

// ---------------- kernel 5: combine fp16 partials + elu ----------------
__global__ __launch_bounds__(256) void k_comb(float* __restrict__ out) {
    const size_t idx = ((size_t)blockIdx.x * 256 + threadIdx.x) * 4;
    const size_t stride = (size_t)N * FOUT;
    float o[4] = {0.f, 0.f, 0.f, 0.f};
#pragma unroll
    for (int sp = 0; sp < JSPLIT; sp++) {
        uint2 u = *(const uint2*)(g_part_h + sp * stride + idx);
        float2 p0 = __half22float2(*(__half2*)&u.x);
        float2 p1 = __half22float2(*(__half2*)&u.y);
        o[0] += p0.x; o[1] += p0.y; o[2] += p1.x; o[3] += p1.y;
    }
    float4 r;
    r.x = o[0] > 0.f ? o[0] : (__expf(o[0]) - 1.f);
    r.y = o[1] > 0.f ? o[1] : (__expf(o[1]) - 1.f);
    r.z = o[2] > 0.f ? o[2] : (__expf(o[2]) - 1.f);
    r.w = o[3] > 0.f ? o[3] : (__expf(o[3]) - 1.f);
    *(float4*)(out + idx) = r;
}

// ---------------- launch ----------------
extern "C" void kernel_launch(void* const* d_in, const int* in_sizes, int n_in,
                              void* d_out, int out_size) {
    const int* adj = (const int*)d_in[0];
    const float* h = (const float*)d_in[1];
    const float* Wm = (const float*)d_in[2];
    const float* b = (const float*)d_in[3];
    const float* a1 = (const float*)d_in[4];
    const float* a2 = (const float*)d_in[5];
    const float* ab = (const float*)d_in[6];
    float* out = (float*)d_out;

    static bool inited = false;
    static void* fsrc_ptr = nullptr;
    static void* fdst_ptr = nullptr;
    if (!inited) {
        cudaFuncSetAttribute(k_attn_h, cudaFuncAttributeMaxDynamicSharedMemorySize, SMEM_AT);
        cudaFuncSetAttribute(k_wh_h, cudaFuncAttributeMaxDynamicSharedMemorySize, SMEM_WH);
        cudaGetSymbolAddress(&fsrc_ptr, g_fsrc);
        cudaGetSymbolAddress(&fdst_ptr, g_fdst);
        inited = true;
    }

    cudaMemsetAsync(fsrc_ptr, 0, N * sizeof(float));
    cudaMemsetAsync(fdst_ptr, 0, N * sizeof(float));
    k_cvt<<<2048 + 128, 256>>>(h, Wm);
    k_wh_h<<<N / 32, 1024, SMEM_WH>>>(b, a1, a2);
    k_prep<<<N, 256>>>(adj, ab);
    k_attn_h<<<dim3(N / 128, JSPLIT), 1024, SMEM_AT>>>();
    k_comb<<<(N * FOUT) / 1024, 256>>>(out);
}

// round 15
// speedup vs baseline: 1.2800x; 1.0046x over previous
#include <cuda_runtime.h>
#include <cuda_bf16.h>
#include <cuda_fp16.h>
#include <cstdint>

#define N 4096
#define FIN 512
#define FOUT 256
#define ALPHA 0.2f
#define JSPLIT 4
#define KCTA (N / JSPLIT)   // 1024
#define NCHUNK (KCTA / 64)  // 16

// ---------------- device scratch ----------------
__device__ float g_fsrc[N];   // zeroed by k_cvt; atomically accumulated; +ab by k_stats
__device__ float g_fdst[N];
__device__ float g_mi[N];
__device__ float g_rz[N];
__device__ unsigned g_mask[N * (N / 32)];                    // 2 MB
__device__ __align__(16) __half g_h_h[N * FIN];              // 4 MB h in fp16
__device__ __align__(16) __half g_W_hi[FIN * FOUT];          // 256 KB
__device__ __align__(16) __half g_W_lo[FIN * FOUT];          // 256 KB
__device__ __align__(16) __half g_wh_h[N * FOUT];            // 2 MB [j][d] fp16
__device__ __align__(16) __half g_part_h[(size_t)JSPLIT * N * FOUT];  // 8 MB fp16 partials

// ---------------- base-ISA PTX helpers ----------------
__device__ __forceinline__ uint32_t smem_u32(const void* p) {
    uint32_t a;
    asm("{ .reg .u64 t; cvta.to.shared.u64 t, %1; cvt.u32.u64 %0, t; }" : "=r"(a) : "l"(p));
    return a;
}
__device__ __forceinline__ void ldm_x4(uint32_t* r, uint32_t addr) {
    asm volatile("ldmatrix.sync.aligned.m8n8.x4.shared.b16 {%0,%1,%2,%3}, [%4];"
                 : "=r"(r[0]), "=r"(r[1]), "=r"(r[2]), "=r"(r[3]) : "r"(addr));
}
__device__ __forceinline__ void ldm_x4_t(uint32_t* r, uint32_t addr) {
    asm volatile("ldmatrix.sync.aligned.m8n8.x4.trans.shared.b16 {%0,%1,%2,%3}, [%4];"
                 : "=r"(r[0]), "=r"(r[1]), "=r"(r[2]), "=r"(r[3]) : "r"(addr));
}
__device__ __forceinline__ void mma_f16(float* c, const uint32_t* a, const uint32_t* b) {
    asm volatile(
        "mma.sync.aligned.m16n8k16.row.col.f32.f16.f16.f32 "
        "{%0,%1,%2,%3}, {%4,%5,%6,%7}, {%8,%9}, {%0,%1,%2,%3};"
        : "+f"(c[0]), "+f"(c[1]), "+f"(c[2]), "+f"(c[3])
        : "r"(a[0]), "r"(a[1]), "r"(a[2]), "r"(a[3]), "r"(b[0]), "r"(b[1]));
}
#define CP_ASYNC16(dst, src) \
    asm volatile("cp.async.cg.shared.global [%0], [%1], 16;" :: "r"(dst), "l"(src))
#define CP_COMMIT() asm volatile("cp.async.commit_group;" ::: "memory")
#define CP_WAIT0() asm volatile("cp.async.wait_group 0;" ::: "memory")

// ---------------- kernel 0: convert h/W + zero f_src/f_dst ------------------
__global__ __launch_bounds__(256) void k_cvt(const float* __restrict__ h,
                                             const float* __restrict__ Wm) {
    const int b = blockIdx.x, t = threadIdx.x;
    if (b < 2048) {  // h: 4096*512 = 2048*1024 floats
        size_t idx = (size_t)b * 1024 + t * 4;
        float4 v = *(const float4*)(h + idx);
        __half2 p0 = __floats2half2_rn(v.x, v.y);
        __half2 p1 = __floats2half2_rn(v.z, v.w);
        *(uint2*)(g_h_h + idx) = make_uint2(*(unsigned*)&p0, *(unsigned*)&p1);
    } else if (b < 2176) {  // W: 512*256 = 128*1024 floats
        size_t idx = (size_t)(b - 2048) * 1024 + t * 4;
        float4 v = *(const float4*)(Wm + idx);
        __half2 h0 = __floats2half2_rn(v.x, v.y);
        __half2 h1 = __floats2half2_rn(v.z, v.w);
        __half2 l0 = __floats2half2_rn(v.x - __half2float(h0.x), v.y - __half2float(h0.y));
        __half2 l1 = __floats2half2_rn(v.z - __half2float(h1.x), v.w - __half2float(h1.y));
        *(uint2*)(g_W_hi + idx) = make_uint2(*(unsigned*)&h0, *(unsigned*)&h1);
        *(uint2*)(g_W_lo + idx) = make_uint2(*(unsigned*)&l0, *(unsigned*)&l1);
    } else {  // zero g_fsrc / g_fdst (8192 floats)
        float4 z = make_float4(0.f, 0.f, 0.f, 0.f);
#pragma unroll
        for (int u = 0; u < 4; u++) {
            ((float4*)g_fsrc)[t * 4 + u] = z;
            ((float4*)g_fdst)[t * 4 + u] = z;
        }
    }
}

// ---------------- kernel 1: wh GEMM via HMMA (h fp16 x W hi/lo) -------------
#define WH_A 0
#define WH_BHI 4608
#define WH_BLO 38400
#define WH_STG 72192
#define SMEM_WH (2 * WH_STG)  // 144384

__global__ __launch_bounds__(1024, 1) void k_wh_h(const float* __restrict__ bias,
                                                  const float* __restrict__ a1,
                                                  const float* __restrict__ a2) {
    extern __shared__ char smem[];
    const uint32_t sbase = smem_u32(smem);
    const int t = threadIdx.x, lane = t & 31, warp = t >> 5;
    const int mg = warp & 1, ns = warp >> 1;
    const int i0 = blockIdx.x * 32;

    auto fill = [&](int c2, uint32_t stg) {
        const int k0 = c2 * 64;
        if (t < 256) {
            int row = t >> 3, cc = t & 7;
            CP_ASYNC16(stg + WH_A + row * 144 + cc * 16,
                       (const void*)(g_h_h + (size_t)(i0 + row) * FIN + k0 + cc * 8));
        }
#pragma unroll
        for (int u = 0; u < 2; u++) {
            int idx = t + 1024 * u;
            int j = idx >> 5, dq = idx & 31;
            uint32_t dst = stg + WH_BHI + j * 528 + dq * 16;
            size_t src = (size_t)(k0 + j) * FOUT + dq * 8;
            CP_ASYNC16(dst, (const void*)(g_W_hi + src));
            CP_ASYNC16(dst + (WH_BLO - WH_BHI), (const void*)(g_W_lo + src));
        }
    };

    float acc[2][4];
#pragma unroll
    for (int b = 0; b < 2; b++)
#pragma unroll
        for (int c = 0; c < 4; c++) acc[b][c] = 0.f;

    const uint32_t a_off = (mg * 16 + (lane & 15)) * 144 + (lane >> 4) * 16;
    const uint32_t b_off = (lane & 15) * 528 + (ns * 16 + (lane >> 4) * 8) * 2;

    fill(0, sbase);
    CP_COMMIT();
    CP_WAIT0();
    __syncthreads();

#pragma unroll 1
    for (int c = 0; c < 8; c++) {
        const uint32_t stg = sbase + (uint32_t)(c & 1) * WH_STG;
        const uint32_t stg2 = sbase + (uint32_t)((c & 1) ^ 1) * WH_STG;
        if (c + 1 < 8) { fill(c + 1, stg2); CP_COMMIT(); }

#pragma unroll
        for (int kk = 0; kk < 4; kk++) {
            uint32_t ah[4], bh[4], bl[4];
            ldm_x4(ah, stg + WH_A + a_off + kk * 32);
            ldm_x4_t(bh, stg + WH_BHI + b_off + kk * 8448);
            ldm_x4_t(bl, stg + WH_BLO + b_off + kk * 8448);
            mma_f16(acc[0], ah, bh);
            mma_f16(acc[1], ah, bh + 2);
            mma_f16(acc[0], ah, bl);
            mma_f16(acc[1], ah, bl + 2);
        }
        CP_WAIT0();
        __syncthreads();
    }

    // epilogue: bias, fp16 store, f-dot atomics
    const int d0 = ns * 16 + (lane & 3) * 2;
    const int d1 = d0 + 8;
    const int ir = i0 + mg * 16 + (lane >> 2);
    float2 bv0 = *(const float2*)(bias + d0);
    float2 bv1 = *(const float2*)(bias + d1);
    float o00 = acc[0][0] + bv0.x, o01 = acc[0][1] + bv0.y;
    float o10 = acc[1][0] + bv1.x, o11 = acc[1][1] + bv1.y;
    float o20 = acc[0][2] + bv0.x, o21 = acc[0][3] + bv0.y;
    float o30 = acc[1][2] + bv1.x, o31 = acc[1][3] + bv1.y;

    __half2 p;
    p = __floats2half2_rn(o00, o01); *(uint32_t*)(g_wh_h + (size_t)ir * FOUT + d0) = *(uint32_t*)&p;
    p = __floats2half2_rn(o10, o11); *(uint32_t*)(g_wh_h + (size_t)ir * FOUT + d1) = *(uint32_t*)&p;
    p = __floats2half2_rn(o20, o21); *(uint32_t*)(g_wh_h + (size_t)(ir + 8) * FOUT + d0) = *(uint32_t*)&p;
    p = __floats2half2_rn(o30, o31); *(uint32_t*)(g_wh_h + (size_t)(ir + 8) * FOUT + d1) = *(uint32_t*)&p;

    float2 x0 = *(const float2*)(a1 + d0), x1 = *(const float2*)(a1 + d1);
    float2 y0 = *(const float2*)(a2 + d0), y1 = *(const float2*)(a2 + d1);
    float s1 = o00 * x0.x + o01 * x0.y + o10 * x1.x + o11 * x1.y;
    float s2 = o00 * y0.x + o01 * y0.y + o10 * y1.x + o11 * y1.y;
    float s1b = o20 * x0.x + o21 * x0.y + o30 * x1.x + o31 * x1.y;
    float s2b = o20 * y0.x + o21 * y0.y + o30 * y1.x + o31 * y1.y;
#pragma unroll
    for (int off = 1; off <= 2; off <<= 1) {
        s1 += __shfl_xor_sync(0xffffffffu, s1, off);
        s2 += __shfl_xor_sync(0xffffffffu, s2, off);
        s1b += __shfl_xor_sync(0xffffffffu, s1b, off);
        s2b += __shfl_xor_sync(0xffffffffu, s2b, off);
    }
    if ((lane & 3) == 0) {
        atomicAdd(g_fsrc + ir, s1);
        atomicAdd(g_fdst + ir, s2);
        atomicAdd(g_fsrc + ir + 8, s1b);
        atomicAdd(g_fdst + ir + 8, s2b);
    }
}

// ---------------- kernel 2a: adj bit-pack (independent; side stream) --------
__global__ __launch_bounds__(256) void k_mask(const int* __restrict__ adj) {
    const int i = blockIdx.x, t = threadIdx.x;
    const int4* arow = (const int4*)(adj + (size_t)i * N);
#pragma unroll
    for (int u = 0; u < 4; u++) {
        int idx = u * 256 + t;
        int4 a = __ldcs(arow + idx);
        unsigned nib = 0;
        if (a.x > 0) nib |= 1u;
        if (a.y > 0) nib |= 2u;
        if (a.z > 0) nib |= 4u;
        if (a.w > 0) nib |= 8u;
        unsigned v = nib << ((t & 7) * 4);
        v |= __shfl_xor_sync(0xffffffffu, v, 1);
        v |= __shfl_xor_sync(0xffffffffu, v, 2);
        v |= __shfl_xor_sync(0xffffffffu, v, 4);
        if ((t & 7) == 0) g_mask[(size_t)i * 128 + u * 32 + (t >> 3)] = v;
    }
}

// ---------------- kernel 2b: softmax stats from mask + fd -------------------
__global__ __launch_bounds__(256) void k_stats(const float* __restrict__ ab) {
    const int i = blockIdx.x, t = threadIdx.x;
    const float fs = g_fsrc[i] + ab[0];
    const float4* fdp = (const float4*)g_fdst;
    __shared__ unsigned mrow[128];
    __shared__ float redm[8];
    __shared__ float reds[8];
    if (t < 128) mrow[t] = g_mask[(size_t)i * 128 + t];
    __syncthreads();

    float fdv[16];
    unsigned bits = 0;
#pragma unroll
    for (int u = 0; u < 4; u++) {
        int idx = u * 256 + t;
        float4 f = fdp[idx];
        fdv[u * 4 + 0] = f.x; fdv[u * 4 + 1] = f.y;
        fdv[u * 4 + 2] = f.z; fdv[u * 4 + 3] = f.w;
        unsigned nib = (mrow[u * 32 + (t >> 3)] >> ((t & 7) * 4)) & 0xFu;
        bits |= nib << (u * 4);
    }

    float mx = -3.4e38f;
#pragma unroll
    for (int v = 0; v < 16; v++)
        if ((bits >> v) & 1u) mx = fmaxf(mx, fdv[v]);
#pragma unroll
    for (int o = 16; o; o >>= 1) mx = fmaxf(mx, __shfl_xor_sync(0xffffffffu, mx, o));
    if ((t & 31) == 0) redm[t >> 5] = mx;
    __syncthreads();
    float mxall = redm[0];
#pragma unroll
    for (int w = 1; w < 8; w++) mxall = fmaxf(mxall, redm[w]);
    float xm = fs + mxall;
    float mi = fmaxf(xm, ALPHA * xm);

    float s = 0.f;
#pragma unroll
    for (int v = 0; v < 16; v++)
        if ((bits >> v) & 1u) {
            float x = fs + fdv[v];
            s += __expf(fmaxf(x, ALPHA * x) - mi);
        }
#pragma unroll
    for (int o = 16; o; o >>= 1) s += __shfl_xor_sync(0xffffffffu, s, o);
    if ((t & 31) == 0) reds[t >> 5] = s;
    __syncthreads();
    if (t == 0) {
        float stot = 0.f;
#pragma unroll
        for (int w = 0; w < 8; w++) stot += reds[w];
        g_mi[i] = mi;
        g_rz[i] = (stot > 0.f) ? (1.f / stot) : 0.f;
        g_fsrc[i] = fs;   // ab-inclusive f_src for k_attn
    }
}

// ---------------- kernel 4: HMMA attention GEMM (fp16, fp16 partials) -------
#define SM_FD 0
#define SM_MASK 4096
#define SM_STG0 20480
#define A_OFF 0
#define B_OFF 18432
#define STG 52224
#define SMEM_AT (SM_STG0 + 2 * STG)  // 124928

__global__ __launch_bounds__(1024, 1) void k_attn_h() {
    extern __shared__ char smem[];
    const uint32_t sbase = smem_u32(smem);
    float* fd_s = (float*)(smem + SM_FD);
    unsigned* mask_s = (unsigned*)(smem + SM_MASK);
    const int t = threadIdx.x;
    const int lane = t & 31, warp = t >> 5;
    const int mw = warp >> 3, nw = warp & 7;
    const int i0 = blockIdx.x * 128;
    const int js = blockIdx.y;
    const int jorg = js * KCTA;

    const int gi = i0 + (t >> 3);
    const float fsi = g_fsrc[gi];
    const float mii = g_mi[gi];
    const float rzi = g_rz[gi];

    if (t < 256) *(float4*)(fd_s + t * 4) = *(const float4*)(g_fdst + jorg + t * 4);
#pragma unroll
    for (int u = 0; u < 4; u++) {
        int idx = t + 1024 * u;
        mask_s[idx] = g_mask[(size_t)(i0 + (idx >> 5)) * 128 + js * 32 + (idx & 31)];
    }
    __syncthreads();

    auto fill_B = [&](int c2, uint32_t stg_s) {
        size_t jg = (size_t)jorg + (size_t)c2 * 64;
#pragma unroll
        for (int u = 0; u < 2; u++) {
            int idx = t + 1024 * u;
            int j = idx >> 5, dq = idx & 31;
            uint32_t dst = stg_s + B_OFF + j * 528 + dq * 16;
            size_t src = (jg + j) * FOUT + dq * 8;
            CP_ASYNC16(dst, (const void*)(g_wh_h + src));
        }
    };
    auto fill_A = [&](int c2, char* stgp) {
        const int row = t >> 3, oct = t & 7;
        unsigned w = mask_s[row * 32 + c2 * 2 + (oct >> 2)] >> ((oct & 3) * 8);
        const float* fdp = fd_s + c2 * 64 + oct * 8;
        uint32_t hv[4];
#pragma unroll
        for (int v = 0; v < 8; v += 2) {
            float e0 = 0.f, e1 = 0.f;
            if ((w >> v) & 1u) {
                float x = fsi + fdp[v];
                e0 = __expf(fmaxf(x, ALPHA * x) - mii) * rzi;
            }
            if ((w >> (v + 1)) & 1u) {
                float x = fsi + fdp[v + 1];
                e1 = __expf(fmaxf(x, ALPHA * x) - mii) * rzi;
            }
            __half2 h2 = __floats2half2_rn(e0, e1);
            hv[v >> 1] = *(uint32_t*)&h2;
        }
        *(uint4*)(stgp + A_OFF + row * 144 + oct * 16) =
            make_uint4(hv[0], hv[1], hv[2], hv[3]);
    };

    float acc[2][4][4];
#pragma unroll
    for (int a = 0; a < 2; a++)
#pragma unroll
        for (int b = 0; b < 4; b++)
#pragma unroll
            for (int c = 0; c < 4; c++) acc[a][b][c] = 0.f;

    const uint32_t a_off = (mw * 32 + (lane & 15)) * 144 + (lane >> 4) * 16;
    const uint32_t b_off = (lane & 15) * 528 + (nw * 32 + (lane >> 4) * 8) * 2;

    fill_B(0, sbase + SM_STG0);
    CP_COMMIT();
    fill_A(0, smem + SM_STG0);
    CP_WAIT0();
    __syncthreads();

#pragma unroll 1
    for (int c = 0; c < NCHUNK; c++) {
        const int s = c & 1;
        const uint32_t stg = SM_STG0 + (uint32_t)s * STG;
        const uint32_t stg2 = SM_STG0 + (uint32_t)(s ^ 1) * STG;
        const uint32_t Aa = sbase + stg + A_OFF;
        const uint32_t Bb = sbase + stg + B_OFF;

        if (c + 1 < NCHUNK) { fill_B(c + 1, sbase + stg2); CP_COMMIT(); }

#pragma unroll
        for (int kk = 0; kk < 4; kk++) {
            uint32_t bh[2][4];
            const uint32_t ao = a_off + kk * 32;
            const uint32_t bo = b_off + kk * 8448;
#pragma unroll
            for (int seg = 0; seg < 2; seg++)
                ldm_x4_t(bh[seg], Bb + bo + seg * 32);
#pragma unroll
            for (int mt = 0; mt < 2; mt++) {
                uint32_t ah[4];
                ldm_x4(ah, Aa + ao + mt * (16 * 144));
#pragma unroll
                for (int nb = 0; nb < 4; nb++) {
                    const uint32_t* bf = &bh[nb >> 1][(nb & 1) * 2];
                    mma_f16(acc[mt][nb], ah, bf);
                }
            }
            if (kk == 0 && c + 1 < NCHUNK) fill_A(c + 1, smem + stg2);
        }

        CP_WAIT0();
        __syncthreads();
    }

    __half* base = g_part_h + (size_t)js * ((size_t)N * FOUT);
#pragma unroll
    for (int mt = 0; mt < 2; mt++) {
        int ir = i0 + mw * 32 + mt * 16 + (lane >> 2);
#pragma unroll
        for (int nb = 0; nb < 4; nb++) {
            int d = nw * 32 + nb * 8 + (lane & 3) * 2;
            __half2 p01 = __floats2half2_rn(acc[mt][nb][0], acc[mt][nb][1]);
            __half2 p23 = __floats2half2_rn(acc[mt][nb][2], acc[mt][nb][3]);
            *(uint32_t*)(base + (size_t)ir * FOUT + d) = *(uint32_t*)&p01;
            *(uint32_t*)(base + (size_t)(ir + 8) * FOUT + d) = *(uint32_t*)&p23;
        }
    }
}

// ---------------- kernel 5: combine fp16 partials + elu ----------------
__global__ __launch_bounds__(256) void k_comb(float* __restrict__ out) {
    const size_t idx = ((size_t)blockIdx.x * 256 + threadIdx.x) * 4;
    const size_t stride = (size_t)N * FOUT;
    float o[4] = {0.f, 0.f, 0.f, 0.f};
#pragma unroll
    for (int sp = 0; sp < JSPLIT; sp++) {
        uint2 u = *(const uint2*)(g_part_h + sp * stride + idx);
        float2 p0 = __half22float2(*(__half2*)&u.x);
        float2 p1 = __half22float2(*(__half2*)&u.y);
        o[0] += p0.x; o[1] += p0.y; o[2] += p1.x; o[3] += p1.y;
    }
    float4 r;
    r.x = o[0] > 0.f ? o[0] : (__expf(o[0]) - 1.f);
    r.y = o[1] > 0.f ? o[1] : (__expf(o[1]) - 1.f);
    r.z = o[2] > 0.f ? o[2] : (__expf(o[2]) - 1.f);
    r.w = o[3] > 0.f ? o[3] : (__expf(o[3]) - 1.f);
    *(float4*)(out + idx) = r;
}

// ---------------- launch: fork-join capture (mask ∥ cvt→wh) ----------------
extern "C" void kernel_launch(void* const* d_in, const int* in_sizes, int n_in,
                              void* d_out, int out_size) {
    const int* adj = (const int*)d_in[0];
    const float* h = (const float*)d_in[1];
    const float* Wm = (const float*)d_in[2];
    const float* b = (const float*)d_in[3];
    const float* a1 = (const float*)d_in[4];
    const float* a2 = (const float*)d_in[5];
    const float* ab = (const float*)d_in[6];
    float* out = (float*)d_out;

    static bool inited = false;
    static cudaStream_t s2;
    static cudaEvent_t e1, e2;
    if (!inited) {
        cudaFuncSetAttribute(k_attn_h, cudaFuncAttributeMaxDynamicSharedMemorySize, SMEM_AT);
        cudaFuncSetAttribute(k_wh_h, cudaFuncAttributeMaxDynamicSharedMemorySize, SMEM_WH);
        cudaStreamCreateWithFlags(&s2, cudaStreamNonBlocking);
        cudaEventCreateWithFlags(&e1, cudaEventDisableTiming);
        cudaEventCreateWithFlags(&e2, cudaEventDisableTiming);
        inited = true;
    }

    // fork: k_mask (adj bit-pack, DRAM-bound) runs concurrently with cvt+wh
    cudaEventRecord(e1, 0);
    cudaStreamWaitEvent(s2, e1, 0);
    k_mask<<<N, 256, 0, s2>>>(adj);
    cudaEventRecord(e2, s2);

    k_cvt<<<2177, 256>>>(h, Wm);
    k_wh_h<<<N / 32, 1024, SMEM_WH>>>(b, a1, a2);

    // join: stats needs both wh-derived f_dst and the mask
    cudaStreamWaitEvent(0, e2, 0);
    k_stats<<<N, 256>>>(ab);
    k_attn_h<<<dim3(N / 128, JSPLIT), 1024, SMEM_AT>>>();
    k_comb<<<(N * FOUT) / 1024, 256>>>(out);
}

// round 16
// speedup vs baseline: 1.5168x; 1.1850x over previous
#include <cuda_runtime.h>
#include <cuda_bf16.h>
#include <cuda_fp16.h>
#include <cstdint>

#define N 4096
#define FIN 512
#define FOUT 256
#define ALPHA 0.2f
#define JSPLIT 4
#define KCTA (N / JSPLIT)   // 1024
#define NCHUNK (KCTA / 64)  // 16

// ---------------- device scratch ----------------
__device__ float g_fsrc[N];   // zeroed by k_cvt; atomically accumulated by k_wh_h
__device__ float g_fdst[N];
__device__ float g_z[N];      // unnormalized softmax row sums (atomic)
__device__ unsigned g_mask[N * (N / 32)];                    // 2 MB
__device__ __align__(16) __half g_h_h[N * FIN];              // 4 MB h in fp16
__device__ __align__(16) __half g_W_hi[FIN * FOUT];          // 256 KB
__device__ __align__(16) __half g_W_lo[FIN * FOUT];          // 256 KB
__device__ __align__(16) __half g_wh_h[N * FOUT];            // 2 MB [j][d] fp16
__device__ __align__(16) __half g_part_h[(size_t)JSPLIT * N * FOUT];  // 8 MB fp16 partials

// ---------------- base-ISA PTX helpers ----------------
__device__ __forceinline__ uint32_t smem_u32(const void* p) {
    uint32_t a;
    asm("{ .reg .u64 t; cvta.to.shared.u64 t, %1; cvt.u32.u64 %0, t; }" : "=r"(a) : "l"(p));
    return a;
}
__device__ __forceinline__ void ldm_x4(uint32_t* r, uint32_t addr) {
    asm volatile("ldmatrix.sync.aligned.m8n8.x4.shared.b16 {%0,%1,%2,%3}, [%4];"
                 : "=r"(r[0]), "=r"(r[1]), "=r"(r[2]), "=r"(r[3]) : "r"(addr));
}
__device__ __forceinline__ void ldm_x4_t(uint32_t* r, uint32_t addr) {
    asm volatile("ldmatrix.sync.aligned.m8n8.x4.trans.shared.b16 {%0,%1,%2,%3}, [%4];"
                 : "=r"(r[0]), "=r"(r[1]), "=r"(r[2]), "=r"(r[3]) : "r"(addr));
}
__device__ __forceinline__ void mma_f16(float* c, const uint32_t* a, const uint32_t* b) {
    asm volatile(
        "mma.sync.aligned.m16n8k16.row.col.f32.f16.f16.f32 "
        "{%0,%1,%2,%3}, {%4,%5,%6,%7}, {%8,%9}, {%0,%1,%2,%3};"
        : "+f"(c[0]), "+f"(c[1]), "+f"(c[2]), "+f"(c[3])
        : "r"(a[0]), "r"(a[1]), "r"(a[2]), "r"(a[3]), "r"(b[0]), "r"(b[1]));
}
#define CP_ASYNC16(dst, src) \
    asm volatile("cp.async.cg.shared.global [%0], [%1], 16;" :: "r"(dst), "l"(src))
#define CP_COMMIT() asm volatile("cp.async.commit_group;" ::: "memory")
#define CP_WAIT0() asm volatile("cp.async.wait_group 0;" ::: "memory")

// ---------------- kernel 0: convert h/W + zero f_src/f_dst/z ----------------
__global__ __launch_bounds__(256) void k_cvt(const float* __restrict__ h,
                                             const float* __restrict__ Wm) {
    const int b = blockIdx.x, t = threadIdx.x;
    if (b < 2048) {  // h: 4096*512 = 2048*1024 floats
        size_t idx = (size_t)b * 1024 + t * 4;
        float4 v = *(const float4*)(h + idx);
        __half2 p0 = __floats2half2_rn(v.x, v.y);
        __half2 p1 = __floats2half2_rn(v.z, v.w);
        *(uint2*)(g_h_h + idx) = make_uint2(*(unsigned*)&p0, *(unsigned*)&p1);
    } else if (b < 2176) {  // W: 512*256 = 128*1024 floats
        size_t idx = (size_t)(b - 2048) * 1024 + t * 4;
        float4 v = *(const float4*)(Wm + idx);
        __half2 h0 = __floats2half2_rn(v.x, v.y);
        __half2 h1 = __floats2half2_rn(v.z, v.w);
        __half2 l0 = __floats2half2_rn(v.x - __half2float(h0.x), v.y - __half2float(h0.y));
        __half2 l1 = __floats2half2_rn(v.z - __half2float(h1.x), v.w - __half2float(h1.y));
        *(uint2*)(g_W_hi + idx) = make_uint2(*(unsigned*)&h0, *(unsigned*)&h1);
        *(uint2*)(g_W_lo + idx) = make_uint2(*(unsigned*)&l0, *(unsigned*)&l1);
    } else {  // zero g_fsrc / g_fdst / g_z (4096 floats each)
        float4 z = make_float4(0.f, 0.f, 0.f, 0.f);
#pragma unroll
        for (int u = 0; u < 4; u++) {
            ((float4*)g_fsrc)[t * 4 + u] = z;
            ((float4*)g_fdst)[t * 4 + u] = z;
            ((float4*)g_z)[t * 4 + u] = z;
        }
    }
}

// ---------------- kernel 1: wh GEMM via HMMA (h fp16 x W hi/lo) -------------
#define WH_A 0
#define WH_BHI 4608
#define WH_BLO 38400
#define WH_STG 72192
#define SMEM_WH (2 * WH_STG)  // 144384

__global__ __launch_bounds__(1024, 1) void k_wh_h(const float* __restrict__ bias,
                                                  const float* __restrict__ a1,
                                                  const float* __restrict__ a2) {
    extern __shared__ char smem[];
    const uint32_t sbase = smem_u32(smem);
    const int t = threadIdx.x, lane = t & 31, warp = t >> 5;
    const int mg = warp & 1, ns = warp >> 1;
    const int i0 = blockIdx.x * 32;

    auto fill = [&](int c2, uint32_t stg) {
        const int k0 = c2 * 64;
        if (t < 256) {
            int row = t >> 3, cc = t & 7;
            CP_ASYNC16(stg + WH_A + row * 144 + cc * 16,
                       (const void*)(g_h_h + (size_t)(i0 + row) * FIN + k0 + cc * 8));
        }
#pragma unroll
        for (int u = 0; u < 2; u++) {
            int idx = t + 1024 * u;
            int j = idx >> 5, dq = idx & 31;
            uint32_t dst = stg + WH_BHI + j * 528 + dq * 16;
            size_t src = (size_t)(k0 + j) * FOUT + dq * 8;
            CP_ASYNC16(dst, (const void*)(g_W_hi + src));
            CP_ASYNC16(dst + (WH_BLO - WH_BHI), (const void*)(g_W_lo + src));
        }
    };

    float acc[2][4];
#pragma unroll
    for (int b = 0; b < 2; b++)
#pragma unroll
        for (int c = 0; c < 4; c++) acc[b][c] = 0.f;

    const uint32_t a_off = (mg * 16 + (lane & 15)) * 144 + (lane >> 4) * 16;
    const uint32_t b_off = (lane & 15) * 528 + (ns * 16 + (lane >> 4) * 8) * 2;

    fill(0, sbase);
    CP_COMMIT();
    CP_WAIT0();
    __syncthreads();

#pragma unroll 1
    for (int c = 0; c < 8; c++) {
        const uint32_t stg = sbase + (uint32_t)(c & 1) * WH_STG;
        const uint32_t stg2 = sbase + (uint32_t)((c & 1) ^ 1) * WH_STG;
        if (c + 1 < 8) { fill(c + 1, stg2); CP_COMMIT(); }

#pragma unroll
        for (int kk = 0; kk < 4; kk++) {
            uint32_t ah[4], bh[4], bl[4];
            ldm_x4(ah, stg + WH_A + a_off + kk * 32);
            ldm_x4_t(bh, stg + WH_BHI + b_off + kk * 8448);
            ldm_x4_t(bl, stg + WH_BLO + b_off + kk * 8448);
            mma_f16(acc[0], ah, bh);
            mma_f16(acc[1], ah, bh + 2);
            mma_f16(acc[0], ah, bl);
            mma_f16(acc[1], ah, bl + 2);
        }
        CP_WAIT0();
        __syncthreads();
    }

    // epilogue: bias, fp16 store, f-dot atomics
    const int d0 = ns * 16 + (lane & 3) * 2;
    const int d1 = d0 + 8;
    const int ir = i0 + mg * 16 + (lane >> 2);
    float2 bv0 = *(const float2*)(bias + d0);
    float2 bv1 = *(const float2*)(bias + d1);
    float o00 = acc[0][0] + bv0.x, o01 = acc[0][1] + bv0.y;
    float o10 = acc[1][0] + bv1.x, o11 = acc[1][1] + bv1.y;
    float o20 = acc[0][2] + bv0.x, o21 = acc[0][3] + bv0.y;
    float o30 = acc[1][2] + bv1.x, o31 = acc[1][3] + bv1.y;

    __half2 p;
    p = __floats2half2_rn(o00, o01); *(uint32_t*)(g_wh_h + (size_t)ir * FOUT + d0) = *(uint32_t*)&p;
    p = __floats2half2_rn(o10, o11); *(uint32_t*)(g_wh_h + (size_t)ir * FOUT + d1) = *(uint32_t*)&p;
    p = __floats2half2_rn(o20, o21); *(uint32_t*)(g_wh_h + (size_t)(ir + 8) * FOUT + d0) = *(uint32_t*)&p;
    p = __floats2half2_rn(o30, o31); *(uint32_t*)(g_wh_h + (size_t)(ir + 8) * FOUT + d1) = *(uint32_t*)&p;

    float2 x0 = *(const float2*)(a1 + d0), x1 = *(const float2*)(a1 + d1);
    float2 y0 = *(const float2*)(a2 + d0), y1 = *(const float2*)(a2 + d1);
    float s1 = o00 * x0.x + o01 * x0.y + o10 * x1.x + o11 * x1.y;
    float s2 = o00 * y0.x + o01 * y0.y + o10 * y1.x + o11 * y1.y;
    float s1b = o20 * x0.x + o21 * x0.y + o30 * x1.x + o31 * x1.y;
    float s2b = o20 * y0.x + o21 * y0.y + o30 * y1.x + o31 * y1.y;
#pragma unroll
    for (int off = 1; off <= 2; off <<= 1) {
        s1 += __shfl_xor_sync(0xffffffffu, s1, off);
        s2 += __shfl_xor_sync(0xffffffffu, s2, off);
        s1b += __shfl_xor_sync(0xffffffffu, s1b, off);
        s2b += __shfl_xor_sync(0xffffffffu, s2b, off);
    }
    if ((lane & 3) == 0) {
        atomicAdd(g_fsrc + ir, s1);
        atomicAdd(g_fdst + ir, s2);
        atomicAdd(g_fsrc + ir + 8, s1b);
        atomicAdd(g_fdst + ir + 8, s2b);
    }
}

// ---------------- kernel 2: adj bit-pack (independent; side stream) ---------
__global__ __launch_bounds__(256) void k_mask(const int* __restrict__ adj) {
    const int i = blockIdx.x, t = threadIdx.x;
    const int4* arow = (const int4*)(adj + (size_t)i * N);
#pragma unroll
    for (int u = 0; u < 4; u++) {
        int idx = u * 256 + t;
        int4 a = __ldcs(arow + idx);
        unsigned nib = 0;
        if (a.x > 0) nib |= 1u;
        if (a.y > 0) nib |= 2u;
        if (a.z > 0) nib |= 4u;
        if (a.w > 0) nib |= 8u;
        unsigned v = nib << ((t & 7) * 4);
        v |= __shfl_xor_sync(0xffffffffu, v, 1);
        v |= __shfl_xor_sync(0xffffffffu, v, 2);
        v |= __shfl_xor_sync(0xffffffffu, v, 4);
        if ((t & 7) == 0) g_mask[(size_t)i * 128 + u * 32 + (t >> 3)] = v;
    }
}

// ---------------- kernel 4: HMMA attention GEMM, unnormalized + fused Z -----
#define SM_FD 0
#define SM_MASK 4096
#define SM_STG0 20480
#define A_OFF 0
#define B_OFF 18432
#define STG 52224
#define SMEM_AT (SM_STG0 + 2 * STG)  // 124928

__global__ __launch_bounds__(1024, 1) void k_attn_h(const float* __restrict__ ab) {
    extern __shared__ char smem[];
    const uint32_t sbase = smem_u32(smem);
    float* fd_s = (float*)(smem + SM_FD);
    unsigned* mask_s = (unsigned*)(smem + SM_MASK);
    const int t = threadIdx.x;
    const int lane = t & 31, warp = t >> 5;
    const int mw = warp >> 3, nw = warp & 7;
    const int i0 = blockIdx.x * 128;
    const int js = blockIdx.y;
    const int jorg = js * KCTA;

    const int gi = i0 + (t >> 3);
    const float fsi = g_fsrc[gi] + ab[0];
    float zacc = 0.f;   // unnormalized row-sum partial (this thread's j values)

    if (t < 256) *(float4*)(fd_s + t * 4) = *(const float4*)(g_fdst + jorg + t * 4);
#pragma unroll
    for (int u = 0; u < 4; u++) {
        int idx = t + 1024 * u;
        mask_s[idx] = g_mask[(size_t)(i0 + (idx >> 5)) * 128 + js * 32 + (idx & 31)];
    }
    __syncthreads();

    auto fill_B = [&](int c2, uint32_t stg_s) {
        size_t jg = (size_t)jorg + (size_t)c2 * 64;
#pragma unroll
        for (int u = 0; u < 2; u++) {
            int idx = t + 1024 * u;
            int j = idx >> 5, dq = idx & 31;
            uint32_t dst = stg_s + B_OFF + j * 528 + dq * 16;
            size_t src = (jg + j) * FOUT + dq * 8;
            CP_ASYNC16(dst, (const void*)(g_wh_h + src));
        }
    };
    // unnormalized weights: w = exp(leaky_relu(fs+fd)); zacc accumulates row sum
    auto fill_A = [&](int c2, char* stgp) {
        const int row = t >> 3, oct = t & 7;
        unsigned w = mask_s[row * 32 + c2 * 2 + (oct >> 2)] >> ((oct & 3) * 8);
        const float* fdp = fd_s + c2 * 64 + oct * 8;
        uint32_t hv[4];
#pragma unroll
        for (int v = 0; v < 8; v += 2) {
            float e0 = 0.f, e1 = 0.f;
            if ((w >> v) & 1u) {
                float x = fsi + fdp[v];
                e0 = __expf(fmaxf(x, ALPHA * x));
            }
            if ((w >> (v + 1)) & 1u) {
                float x = fsi + fdp[v + 1];
                e1 = __expf(fmaxf(x, ALPHA * x));
            }
            zacc += e0 + e1;
            __half2 h2 = __floats2half2_rn(e0, e1);
            hv[v >> 1] = *(uint32_t*)&h2;
        }
        *(uint4*)(stgp + A_OFF + row * 144 + oct * 16) =
            make_uint4(hv[0], hv[1], hv[2], hv[3]);
    };

    float acc[2][4][4];
#pragma unroll
    for (int a = 0; a < 2; a++)
#pragma unroll
        for (int b = 0; b < 4; b++)
#pragma unroll
            for (int c = 0; c < 4; c++) acc[a][b][c] = 0.f;

    const uint32_t a_off = (mw * 32 + (lane & 15)) * 144 + (lane >> 4) * 16;
    const uint32_t b_off = (lane & 15) * 528 + (nw * 32 + (lane >> 4) * 8) * 2;

    fill_B(0, sbase + SM_STG0);
    CP_COMMIT();
    fill_A(0, smem + SM_STG0);
    CP_WAIT0();
    __syncthreads();

#pragma unroll 1
    for (int c = 0; c < NCHUNK; c++) {
        const int s = c & 1;
        const uint32_t stg = SM_STG0 + (uint32_t)s * STG;
        const uint32_t stg2 = SM_STG0 + (uint32_t)(s ^ 1) * STG;
        const uint32_t Aa = sbase + stg + A_OFF;
        const uint32_t Bb = sbase + stg + B_OFF;

        if (c + 1 < NCHUNK) { fill_B(c + 1, sbase + stg2); CP_COMMIT(); }

#pragma unroll
        for (int kk = 0; kk < 4; kk++) {
            uint32_t bh[2][4];
            const uint32_t ao = a_off + kk * 32;
            const uint32_t bo = b_off + kk * 8448;
#pragma unroll
            for (int seg = 0; seg < 2; seg++)
                ldm_x4_t(bh[seg], Bb + bo + seg * 32);
#pragma unroll
            for (int mt = 0; mt < 2; mt++) {
                uint32_t ah[4];
                ldm_x4(ah, Aa + ao + mt * (16 * 144));
#pragma unroll
                for (int nb = 0; nb < 4; nb++) {
                    const uint32_t* bf = &bh[nb >> 1][(nb & 1) * 2];
                    mma_f16(acc[mt][nb], ah, bf);
                }
            }
            if (kk == 0 && c + 1 < NCHUNK) fill_A(c + 1, smem + stg2);
        }

        CP_WAIT0();
        __syncthreads();
    }

    // Z partial: reduce across the 8 octs of this row (consecutive lanes)
#pragma unroll
    for (int off = 4; off; off >>= 1)
        zacc += __shfl_down_sync(0xffffffffu, zacc, off, 8);
    if ((t & 7) == 0) atomicAdd(g_z + gi, zacc);

    __half* base = g_part_h + (size_t)js * ((size_t)N * FOUT);
#pragma unroll
    for (int mt = 0; mt < 2; mt++) {
        int ir = i0 + mw * 32 + mt * 16 + (lane >> 2);
#pragma unroll
        for (int nb = 0; nb < 4; nb++) {
            int d = nw * 32 + nb * 8 + (lane & 3) * 2;
            __half2 p01 = __floats2half2_rn(acc[mt][nb][0], acc[mt][nb][1]);
            __half2 p23 = __floats2half2_rn(acc[mt][nb][2], acc[mt][nb][3]);
            *(uint32_t*)(base + (size_t)ir * FOUT + d) = *(uint32_t*)&p01;
            *(uint32_t*)(base + (size_t)(ir + 8) * FOUT + d) = *(uint32_t*)&p23;
        }
    }
}

// ---------------- kernel 5: combine fp16 partials, normalize, elu -----------
__global__ __launch_bounds__(256) void k_comb(float* __restrict__ out) {
    const size_t idx = ((size_t)blockIdx.x * 256 + threadIdx.x) * 4;
    const size_t stride = (size_t)N * FOUT;
    const int row = (int)(idx >> 8);
    float zr = g_z[row];
    float rz = (zr > 0.f) ? (1.f / zr) : 0.f;
    float o[4] = {0.f, 0.f, 0.f, 0.f};
#pragma unroll
    for (int sp = 0; sp < JSPLIT; sp++) {
        uint2 u = *(const uint2*)(g_part_h + sp * stride + idx);
        float2 p0 = __half22float2(*(__half2*)&u.x);
        float2 p1 = __half22float2(*(__half2*)&u.y);
        o[0] += p0.x; o[1] += p0.y; o[2] += p1.x; o[3] += p1.y;
    }
    float4 r;
    o[0] *= rz; o[1] *= rz; o[2] *= rz; o[3] *= rz;
    r.x = o[0] > 0.f ? o[0] : (__expf(o[0]) - 1.f);
    r.y = o[1] > 0.f ? o[1] : (__expf(o[1]) - 1.f);
    r.z = o[2] > 0.f ? o[2] : (__expf(o[2]) - 1.f);
    r.w = o[3] > 0.f ? o[3] : (__expf(o[3]) - 1.f);
    *(float4*)(out + idx) = r;
}

// ---------------- launch: fork-join capture (mask ∥ cvt→wh) ----------------
extern "C" void kernel_launch(void* const* d_in, const int* in_sizes, int n_in,
                              void* d_out, int out_size) {
    const int* adj = (const int*)d_in[0];
    const float* h = (const float*)d_in[1];
    const float* Wm = (const float*)d_in[2];
    const float* b = (const float*)d_in[3];
    const float* a1 = (const float*)d_in[4];
    const float* a2 = (const float*)d_in[5];
    const float* ab = (const float*)d_in[6];
    float* out = (float*)d_out;

    static bool inited = false;
    static cudaStream_t s2;
    static cudaEvent_t e1, e2;
    if (!inited) {
        cudaFuncSetAttribute(k_attn_h, cudaFuncAttributeMaxDynamicSharedMemorySize, SMEM_AT);
        cudaFuncSetAttribute(k_wh_h, cudaFuncAttributeMaxDynamicSharedMemorySize, SMEM_WH);
        cudaStreamCreateWithFlags(&s2, cudaStreamNonBlocking);
        cudaEventCreateWithFlags(&e1, cudaEventDisableTiming);
        cudaEventCreateWithFlags(&e2, cudaEventDisableTiming);
        inited = true;
    }

    // fork: k_mask (adj bit-pack, DRAM-bound) runs concurrently with cvt+wh
    cudaEventRecord(e1, 0);
    cudaStreamWaitEvent(s2, e1, 0);
    k_mask<<<N, 256, 0, s2>>>(adj);
    cudaEventRecord(e2, s2);

    k_cvt<<<2177, 256>>>(h, Wm);
    k_wh_h<<<N / 32, 1024, SMEM_WH>>>(b, a1, a2);

    // join: attention needs the mask
    cudaStreamWaitEvent(0, e2, 0);
    k_attn_h<<<dim3(N / 128, JSPLIT), 1024, SMEM_AT>>>(ab);
    k_comb<<<(N * FOUT) / 1024, 256>>>(out);
}